// round 7
// baseline (speedup 1.0000x reference)
#include <cuda_runtime.h>
#include <math.h>
#include <stdint.h>

// Problem constants
#define B_      8
#define SEQ_    16384
#define D_      384
#define H_      8
#define C_      48
#define TOK_    (B_ * SEQ_)          // 131072

// ---------------- scratch (static device globals; no allocs allowed) ----------------
__device__ float g_q[(size_t)TOK_ * D_];           // 201 MB : q = x @ Wq
__device__ float g_xr[(size_t)TOK_ * D_];          // 201 MB : x rounded to tf32
__device__ float g_ctx[B_ * H_ * C_ * C_];         // unnormalized k^T v context
__device__ float g_sum[B_ * H_ * C_];              // sum of exp(k) over tokens
__device__ float g_Wtq[3 * D_ * D_];               // W_qkv^T, tf32-rounded  [1152][384]
__device__ float g_Wtp[D_ * D_];                   // W_proj^T, tf32-rounded

__device__ __forceinline__ float f2tf32(float x) {
    uint32_t y;
    asm("cvt.rna.tf32.f32 %0, %1;" : "=r"(y) : "f"(x));
    return __uint_as_float(y);
}
__device__ __forceinline__ uint32_t smem_u32(const void* p) {
    uint32_t a;
    asm("{ .reg .u64 t; cvta.to.shared.u64 t, %1; cvt.u32.u64 %0, t; }" : "=r"(a) : "l"(p));
    return a;
}
__device__ __forceinline__ void cp_async16(uint32_t dst, const void* src) {
    asm volatile("cp.async.cg.shared.global [%0], [%1], 16;" :: "r"(dst), "l"(src));
}
__device__ __forceinline__ void mma_tf32(float* c, const uint32_t* a, const uint32_t* b) {
    asm volatile(
        "mma.sync.aligned.m16n8k8.row.col.f32.tf32.tf32.f32 "
        "{%0,%1,%2,%3}, {%4,%5,%6,%7}, {%8,%9}, {%0,%1,%2,%3};"
        : "+f"(c[0]), "+f"(c[1]), "+f"(c[2]), "+f"(c[3])
        : "r"(a[0]), "r"(a[1]), "r"(a[2]), "r"(a[3]), "r"(b[0]), "r"(b[1]));
}

// ---------------- zero the atomic accumulators (graph replays!) ----------------
__global__ void zero_ctx_kernel() {
    int i = blockIdx.x * 256 + threadIdx.x;
    if (i < B_ * H_ * C_ * C_) g_ctx[i] = 0.0f;
    if (i < B_ * H_ * C_)      g_sum[i] = 0.0f;
}

// ---------------- round x to tf32 (streaming) ----------------
__global__ void round_tf32_kernel(const float4* __restrict__ src, float4* __restrict__ dst, int n4) {
    int i = blockIdx.x * 256 + threadIdx.x;
    if (i < n4) {
        float4 v = src[i];
        v.x = f2tf32(v.x); v.y = f2tf32(v.y); v.z = f2tf32(v.z); v.w = f2tf32(v.w);
        dst[i] = v;
    }
}

// ---------------- weight transpose + tf32 round: src[R][Ccols] -> dst[Ccols][R] ----------------
__global__ void transpose_kernel(const float* __restrict__ src, float* __restrict__ dst,
                                 int R, int Ccols) {
    __shared__ float t[32][33];
    int bx = blockIdx.x * 32, by = blockIdx.y * 32;
    int tx = threadIdx.x, ty = threadIdx.y;
#pragma unroll
    for (int j = 0; j < 32; j += 8)
        t[ty + j][tx] = src[(size_t)(by + ty + j) * Ccols + bx + tx];
    __syncthreads();
#pragma unroll
    for (int j = 0; j < 32; j += 8)
        dst[(size_t)(bx + ty + j) * R + by + tx] = f2tf32(t[tx][ty + j]);
}

// ================= tf32 mma.sync GEMM (block 128x128, BK=32, 8 warps 2x4, warp 64x32) =================
#define BM_ 128
#define BN_ 128
#define BK_ 32
#define PADS_ 36

template <int K, int N, int HAS_BIAS>
__global__ void __launch_bounds__(256, 2)
gemm_mma(const float* __restrict__ A, const float* __restrict__ Bt,
         const float* __restrict__ bias, float* __restrict__ Cm)
{
    extern __shared__ float smem[];
    float* As = smem;
    float* Bs = smem + 2 * BM_ * PADS_;

    const int tid = threadIdx.x;
    const int wid = tid >> 5;
    const int lane = tid & 31;
    const int m0 = blockIdx.y * BM_;
    const int n0 = blockIdx.x * BN_;
    const int wm = (wid & 1) * 64;
    const int wn = (wid >> 1) * 32;
    const int lr = lane >> 2;
    const int lc = lane & 3;
    const int gr = tid >> 3;
    const int gc = (tid & 7) * 4;

    const uint32_t as_base = smem_u32(As);
    const uint32_t bs_base = smem_u32(Bs);

    float acc[4][4][4];
#pragma unroll
    for (int i = 0; i < 4; i++)
#pragma unroll
        for (int j = 0; j < 4; j++)
#pragma unroll
            for (int r = 0; r < 4; r++) acc[i][j][r] = 0.0f;

    constexpr int nch = K / BK_;

    {
#pragma unroll
        for (int i = 0; i < 4; i++) {
            int row = gr + i * 32;
            cp_async16(as_base + (row * PADS_ + gc) * 4, &A[(size_t)(m0 + row) * K + gc]);
            cp_async16(bs_base + (row * PADS_ + gc) * 4, &Bt[(size_t)(n0 + row) * K + gc]);
        }
        asm volatile("cp.async.commit_group;");
    }

#pragma unroll
    for (int c = 0; c < nch; c++) {
        asm volatile("cp.async.wait_group 0;");
        __syncthreads();

        if (c + 1 < nch) {
            const int k0 = (c + 1) * BK_;
            const int buf = (c + 1) & 1;
            const uint32_t ab = as_base + buf * BM_ * PADS_ * 4;
            const uint32_t bb = bs_base + buf * BN_ * PADS_ * 4;
#pragma unroll
            for (int i = 0; i < 4; i++) {
                int row = gr + i * 32;
                cp_async16(ab + (row * PADS_ + gc) * 4, &A[(size_t)(m0 + row) * K + k0 + gc]);
                cp_async16(bb + (row * PADS_ + gc) * 4, &Bt[(size_t)(n0 + row) * K + k0 + gc]);
            }
            asm volatile("cp.async.commit_group;");
        }

        const float* as = As + (c & 1) * BM_ * PADS_;
        const float* bs = Bs + (c & 1) * BN_ * PADS_;

#pragma unroll
        for (int ks = 0; ks < 4; ks++) {
            const int kk = ks * 8 + lc;
            uint32_t afr[4][4];
#pragma unroll
            for (int mi = 0; mi < 4; mi++) {
                int r = wm + mi * 16 + lr;
                afr[mi][0] = __float_as_uint(as[r * PADS_ + kk]);
                afr[mi][1] = __float_as_uint(as[(r + 8) * PADS_ + kk]);
                afr[mi][2] = __float_as_uint(as[r * PADS_ + kk + 4]);
                afr[mi][3] = __float_as_uint(as[(r + 8) * PADS_ + kk + 4]);
            }
            uint32_t bfr[4][2];
#pragma unroll
            for (int nj = 0; nj < 4; nj++) {
                int nn = wn + nj * 8 + lr;
                bfr[nj][0] = __float_as_uint(bs[nn * PADS_ + kk]);
                bfr[nj][1] = __float_as_uint(bs[nn * PADS_ + kk + 4]);
            }
#pragma unroll
            for (int mi = 0; mi < 4; mi++)
#pragma unroll
                for (int nj = 0; nj < 4; nj++)
                    mma_tf32(acc[mi][nj], afr[mi], bfr[nj]);
        }
        __syncthreads();
    }

#pragma unroll
    for (int mi = 0; mi < 4; mi++) {
        const int r0 = m0 + wm + mi * 16 + lr;
#pragma unroll
        for (int nj = 0; nj < 4; nj++) {
            const int col = n0 + wn + nj * 8 + lc * 2;
            float2 b2 = make_float2(0.f, 0.f);
            if (HAS_BIAS) b2 = *(const float2*)&bias[col];
            float2 v0 = make_float2(acc[mi][nj][0] + b2.x, acc[mi][nj][1] + b2.y);
            float2 v1 = make_float2(acc[mi][nj][2] + b2.x, acc[mi][nj][3] + b2.y);
            *(float2*)&Cm[(size_t)r0 * N + col] = v0;
            *(float2*)&Cm[(size_t)(r0 + 8) * N + col] = v1;
        }
    }
}

// ================= fused kv-GEMM + ctx kernel (unchanged from R6) =================
#define KVN_ 192
#define ST_  132
#define KV_SMEM_FLOATS (2 * 96 * ST_)

__global__ void __launch_bounds__(256, 1)
kv_ctx_kernel()
{
    extern __shared__ float smem[];
    float* As = smem;
    float* Bs = smem + 2 * BM_ * PADS_;
    float* eT = smem;
    float* vT = smem + 96 * ST_;

    const int tid = threadIdx.x;
    const int wid = tid >> 5;
    const int lane = tid & 31;
    const int cg = blockIdx.x;
    const int ss = blockIdx.y;
    const int lr = lane >> 2;
    const int lc = lane & 3;
    const int wm = (wid & 1) * 64;
    const int wn = (wid >> 2) * 0 + (wid >> 1) * 48;
    const int gr = tid >> 3;
    const int gc = (tid & 7) * 4;

    const uint32_t as_base = smem_u32(As);
    const uint32_t bs_base = smem_u32(Bs);

    const float* Wk = g_Wtq + (size_t)(D_ + cg * 96) * D_;
    const float* Wv = g_Wtq + (size_t)(2 * D_ + cg * 96) * D_;

    const int batch = ss / 32;

    float ctxa[5][4];
#pragma unroll
    for (int i = 0; i < 5; i++)
#pragma unroll
        for (int r = 0; r < 4; r++) ctxa[i][r] = 0.0f;
    float ssum = 0.0f;

    for (int rb = 0; rb < 4; rb++) {
        const size_t tok0 = ((size_t)ss * 4 + rb) * 128;
        const float* A = g_xr + tok0 * D_;

        float acc[4][6][4];
#pragma unroll
        for (int i = 0; i < 4; i++)
#pragma unroll
            for (int j = 0; j < 6; j++)
#pragma unroll
                for (int r = 0; r < 4; r++) acc[i][j][r] = 0.0f;

        {
#pragma unroll
            for (int i = 0; i < 4; i++) {
                int row = gr + i * 32;
                cp_async16(as_base + (row * PADS_ + gc) * 4, &A[(size_t)row * D_ + gc]);
            }
#pragma unroll
            for (int i = 0; i < 6; i++) {
                int row = gr + i * 32;
                const float* src = (row < 96) ? &Wk[(size_t)row * D_ + gc]
                                              : &Wv[(size_t)(row - 96) * D_ + gc];
                cp_async16(bs_base + (row * PADS_ + gc) * 4, src);
            }
            asm volatile("cp.async.commit_group;");
        }

#pragma unroll
        for (int c = 0; c < D_ / BK_; c++) {
            asm volatile("cp.async.wait_group 0;");
            __syncthreads();

            if (c + 1 < D_ / BK_) {
                const int k0 = (c + 1) * BK_;
                const int buf = (c + 1) & 1;
                const uint32_t ab = as_base + buf * BM_ * PADS_ * 4;
                const uint32_t bb = bs_base + buf * KVN_ * PADS_ * 4;
#pragma unroll
                for (int i = 0; i < 4; i++) {
                    int row = gr + i * 32;
                    cp_async16(ab + (row * PADS_ + gc) * 4, &A[(size_t)row * D_ + k0 + gc]);
                }
#pragma unroll
                for (int i = 0; i < 6; i++) {
                    int row = gr + i * 32;
                    const float* src = (row < 96) ? &Wk[(size_t)row * D_ + k0 + gc]
                                                  : &Wv[(size_t)(row - 96) * D_ + k0 + gc];
                    cp_async16(bb + (row * PADS_ + gc) * 4, src);
                }
                asm volatile("cp.async.commit_group;");
            }

            const float* as = As + (c & 1) * BM_ * PADS_;
            const float* bs = Bs + (c & 1) * KVN_ * PADS_;

#pragma unroll
            for (int ks = 0; ks < 4; ks++) {
                const int kk = ks * 8 + lc;
                uint32_t afr[4][4];
#pragma unroll
                for (int mi = 0; mi < 4; mi++) {
                    int r = wm + mi * 16 + lr;
                    afr[mi][0] = __float_as_uint(as[r * PADS_ + kk]);
                    afr[mi][1] = __float_as_uint(as[(r + 8) * PADS_ + kk]);
                    afr[mi][2] = __float_as_uint(as[r * PADS_ + kk + 4]);
                    afr[mi][3] = __float_as_uint(as[(r + 8) * PADS_ + kk + 4]);
                }
                uint32_t bfr[6][2];
#pragma unroll
                for (int nj = 0; nj < 6; nj++) {
                    int nn = wn + nj * 8 + lr;
                    bfr[nj][0] = __float_as_uint(bs[nn * PADS_ + kk]);
                    bfr[nj][1] = __float_as_uint(bs[nn * PADS_ + kk + 4]);
                }
#pragma unroll
                for (int mi = 0; mi < 4; mi++)
#pragma unroll
                    for (int nj = 0; nj < 6; nj++)
                        mma_tf32(acc[mi][nj], afr[mi], bfr[nj]);
            }
            __syncthreads();
        }

#pragma unroll
        for (int mi = 0; mi < 4; mi++) {
#pragma unroll
            for (int nj = 0; nj < 6; nj++) {
#pragma unroll
                for (int r = 0; r < 4; r++) {
                    int ch = wn + nj * 8 + lc * 2 + (r & 1);
                    int tl = wm + mi * 16 + lr + ((r >> 1) ? 8 : 0);
                    if (wid < 4) {
                        eT[ch * ST_ + tl] = f2tf32(__expf(acc[mi][nj][r]));
                    } else {
                        vT[(ch - 96) * ST_ + tl] = f2tf32(acc[mi][nj][r]);
                    }
                }
            }
        }
        __syncthreads();

#pragma unroll
        for (int i = 0; i < 5; i++) {
            int t = wid + 8 * i;
            if (t < 36) {
                int head = t / 18, rem = t % 18;
                int mi = rem / 6, nj = rem % 6;
                const float* ea = eT + (head * 48 + mi * 16) * ST_;
                const float* vb = vT + (head * 48 + nj * 8) * ST_;
#pragma unroll
                for (int ks = 0; ks < 16; ks++) {
                    const int kk = ks * 8 + lc;
                    uint32_t a[4], b[2];
                    a[0] = __float_as_uint(ea[lr * ST_ + kk]);
                    a[1] = __float_as_uint(ea[(lr + 8) * ST_ + kk]);
                    a[2] = __float_as_uint(ea[lr * ST_ + kk + 4]);
                    a[3] = __float_as_uint(ea[(lr + 8) * ST_ + kk + 4]);
                    b[0] = __float_as_uint(vb[lr * ST_ + kk]);
                    b[1] = __float_as_uint(vb[lr * ST_ + kk + 4]);
                    mma_tf32(ctxa[i], a, b);
                }
            }
        }

        if (tid < 96) {
            const float* row = eT + tid * ST_;
            float s = 0.0f;
#pragma unroll
            for (int j = 0; j < 32; j++) {
                float4 v = *(const float4*)&row[j * 4];
                s += (v.x + v.y) + (v.z + v.w);
            }
            ssum += s;
        }
        __syncthreads();
    }

#pragma unroll
    for (int i = 0; i < 5; i++) {
        int t = wid + 8 * i;
        if (t < 36) {
            int head = t / 18, rem = t % 18;
            int mi = rem / 6, nj = rem % 6;
            int bh = (batch * H_ + cg * 2 + head);
#pragma unroll
            for (int r = 0; r < 4; r++) {
                int c = mi * 16 + lr + ((r >> 1) ? 8 : 0);
                int d = nj * 8 + lc * 2 + (r & 1);
                atomicAdd(&g_ctx[((size_t)bh * C_ + c) * C_ + d], ctxa[i][r]);
            }
        }
    }
    if (tid < 96) {
        int head = tid / 48;
        atomicAdd(&g_sum[(batch * H_ + cg * 2 + head) * C_ + tid % 48], ssum);
    }
}

// ================= fused attn + proj kernel =================
// CTA = 64 tokens. Phases:
//  1. at[64][388] = tf32(exp(q))           (all 8 heads)
//  2. sinv, ctxnT[8][48][52] (normalized, transposed, tf32), srow2[64][8]
//  3. per-warp attn MMA (warp h: M=64 N=48 K=48), in-place normalized write-back
//  4. proj GEMM: out[64x384] = at @ WtpT, A from smem, Wproj streamed (BK=32 x2 buf)
#define AT_ST  388
#define CTX_ST 52
#define AP_AT_F    (64 * AT_ST)                 // 24832
#define AP_CTX_F   (H_ * C_ * CTX_ST)           // 19968
#define AP_WBUF_F  (2 * 128 * PADS_)            // 9216
#define AP_SMEM_F  (AP_AT_F + AP_CTX_F + AP_WBUF_F + 512 + 384)
#define AP_SMEM_BYTES (AP_SMEM_F * 4)           // 219648

__global__ void __launch_bounds__(256, 1)
attn_proj_kernel(const float* __restrict__ bias, float* __restrict__ out)
{
    extern __shared__ float smem[];
    float* at    = smem;
    float* ctxnT = smem + AP_AT_F;
    float* wbuf  = ctxnT + AP_CTX_F;
    float* srow2 = wbuf + AP_WBUF_F;            // [64][8] : 1/rowsum per (row, head)
    float* sinv  = srow2 + 512;                 // [8*48]

    const int tid = threadIdx.x;
    const int wid = tid >> 5;
    const int lane = tid & 31;
    const int lr = lane >> 2;
    const int lc = lane & 3;
    const size_t tok0 = (size_t)blockIdx.x * 64;
    const int batch = blockIdx.x / (SEQ_ / 64);

    const uint32_t wbuf_base = smem_u32(wbuf);

    // ---- 1) at = tf32(exp(q)) ----
    {
        const float* qb = g_q + tok0 * D_;
        for (int idx = tid; idx < 64 * 96; idx += 256) {
            int r = idx / 96, c4 = idx % 96;
            float4 v = *(const float4*)&qb[(size_t)r * D_ + c4 * 4];
            v.x = f2tf32(__expf(v.x)); v.y = f2tf32(__expf(v.y));
            v.z = f2tf32(__expf(v.z)); v.w = f2tf32(__expf(v.w));
            *(float4*)&at[r * AT_ST + c4 * 4] = v;
        }
    }
    // ---- 2a) sinv ----
    for (int idx = tid; idx < H_ * C_; idx += 256)
        sinv[idx] = 1.0f / g_sum[batch * (H_ * C_) + idx];
    __syncthreads();

    // ---- 2b) ctxnT[h][d][c] = tf32(ctx[h][c][d] * sinv[h][c]) ----
    {
        const float* cb = g_ctx + (size_t)batch * (H_ * C_ * C_);
        for (int idx = tid; idx < H_ * C_ * C_; idx += 256) {
            int h = idx / (C_ * C_), rem = idx % (C_ * C_);
            int c = rem / C_, d = rem % C_;
            ctxnT[h * (C_ * CTX_ST) + d * CTX_ST + c] =
                f2tf32(cb[h * (C_ * C_) + c * C_ + d] * sinv[h * C_ + c]);
        }
    }
    // ---- 2c) srow2 + prefetch proj chunk 0 ----
    {
        const int gr2 = tid >> 3;
        const int gc2 = (tid & 7) * 4;
#pragma unroll
        for (int i = 0; i < 4; i++) {
            int row = gr2 + i * 32;
            cp_async16(wbuf_base + (row * PADS_ + gc2) * 4, &g_Wtp[(size_t)row * D_ + gc2]);
        }
        asm volatile("cp.async.commit_group;");
    }
    __syncthreads();
    for (int p = tid; p < 512; p += 256) {
        int r = p >> 3, h = p & 7;
        const float* rowp = at + r * AT_ST + h * C_;
        float s = 0.0f;
#pragma unroll
        for (int c = 0; c < C_; c++) s += rowp[c];
        srow2[p] = 1.0f / s;
    }
    __syncthreads();

    // ---- 3) attn MMA: warp h computes head h, in-place write ----
    {
        const int h = wid;
        const float* Ah = at + h * C_;
        const float* Bh = ctxnT + h * (C_ * CTX_ST);
        float acc[4][6][4];
#pragma unroll
        for (int i = 0; i < 4; i++)
#pragma unroll
            for (int j = 0; j < 6; j++)
#pragma unroll
                for (int r = 0; r < 4; r++) acc[i][j][r] = 0.0f;

#pragma unroll
        for (int ks = 0; ks < 6; ks++) {
            const int kk = ks * 8 + lc;
            uint32_t afr[4][4];
#pragma unroll
            for (int mi = 0; mi < 4; mi++) {
                int r = mi * 16 + lr;
                afr[mi][0] = __float_as_uint(Ah[r * AT_ST + kk]);
                afr[mi][1] = __float_as_uint(Ah[(r + 8) * AT_ST + kk]);
                afr[mi][2] = __float_as_uint(Ah[r * AT_ST + kk + 4]);
                afr[mi][3] = __float_as_uint(Ah[(r + 8) * AT_ST + kk + 4]);
            }
            uint32_t bfr[6][2];
#pragma unroll
            for (int nj = 0; nj < 6; nj++) {
                int nn = nj * 8 + lr;
                bfr[nj][0] = __float_as_uint(Bh[nn * CTX_ST + kk]);
                bfr[nj][1] = __float_as_uint(Bh[nn * CTX_ST + kk + 4]);
            }
#pragma unroll
            for (int mi = 0; mi < 4; mi++)
#pragma unroll
                for (int nj = 0; nj < 6; nj++)
                    mma_tf32(acc[mi][nj], afr[mi], bfr[nj]);
        }
        __syncwarp();
#pragma unroll
        for (int mi = 0; mi < 4; mi++) {
            const int ra = mi * 16 + lr;
            const float sa = srow2[ra * 8 + h];
            const float sb = srow2[(ra + 8) * 8 + h];
#pragma unroll
            for (int nj = 0; nj < 6; nj++) {
                const int col = h * C_ + nj * 8 + lc * 2;
                at[ra * AT_ST + col]       = f2tf32(acc[mi][nj][0] * sa);
                at[ra * AT_ST + col + 1]   = f2tf32(acc[mi][nj][1] * sa);
                at[(ra + 8) * AT_ST + col]     = f2tf32(acc[mi][nj][2] * sb);
                at[(ra + 8) * AT_ST + col + 1] = f2tf32(acc[mi][nj][3] * sb);
            }
        }
    }
    __syncthreads();

    // ---- 4) proj GEMM over 3 n-tiles of 128 ----
    const int wm = (wid & 1) * 32;
    const int wn = (wid >> 1) * 32;
    const int gr2 = tid >> 3;
    const int gc2 = (tid & 7) * 4;

#pragma unroll
    for (int nt = 0; nt < 3; nt++) {
        const int n0 = nt * 128;
        if (nt > 0) {
#pragma unroll
            for (int i = 0; i < 4; i++) {
                int row = gr2 + i * 32;
                cp_async16(wbuf_base + (row * PADS_ + gc2) * 4,
                           &g_Wtp[(size_t)(n0 + row) * D_ + gc2]);
            }
            asm volatile("cp.async.commit_group;");
        }

        float acc[2][4][4];
#pragma unroll
        for (int i = 0; i < 2; i++)
#pragma unroll
            for (int j = 0; j < 4; j++)
#pragma unroll
                for (int r = 0; r < 4; r++) acc[i][j][r] = 0.0f;

#pragma unroll
        for (int c = 0; c < 12; c++) {
            asm volatile("cp.async.wait_group 0;");
            __syncthreads();

            if (c + 1 < 12) {
                const int k0 = (c + 1) * BK_;
                const uint32_t bb = wbuf_base + ((c + 1) & 1) * 128 * PADS_ * 4;
#pragma unroll
                for (int i = 0; i < 4; i++) {
                    int row = gr2 + i * 32;
                    cp_async16(bb + (row * PADS_ + gc2) * 4,
                               &g_Wtp[(size_t)(n0 + row) * D_ + k0 + gc2]);
                }
                asm volatile("cp.async.commit_group;");
            }

            const float* bs = wbuf + (c & 1) * 128 * PADS_;

#pragma unroll
            for (int ks = 0; ks < 4; ks++) {
                const int kk = c * BK_ + ks * 8 + lc;
                const int kw = ks * 8 + lc;
                uint32_t afr[2][4];
#pragma unroll
                for (int mi = 0; mi < 2; mi++) {
                    int r = wm + mi * 16 + lr;
                    afr[mi][0] = __float_as_uint(at[r * AT_ST + kk]);
                    afr[mi][1] = __float_as_uint(at[(r + 8) * AT_ST + kk]);
                    afr[mi][2] = __float_as_uint(at[r * AT_ST + kk + 4]);
                    afr[mi][3] = __float_as_uint(at[(r + 8) * AT_ST + kk + 4]);
                }
                uint32_t bfr[4][2];
#pragma unroll
                for (int nj = 0; nj < 4; nj++) {
                    int nn = wn + nj * 8 + lr;
                    bfr[nj][0] = __float_as_uint(bs[nn * PADS_ + kw]);
                    bfr[nj][1] = __float_as_uint(bs[nn * PADS_ + kw + 4]);
                }
#pragma unroll
                for (int mi = 0; mi < 2; mi++)
#pragma unroll
                    for (int nj = 0; nj < 4; nj++)
                        mma_tf32(acc[mi][nj], afr[mi], bfr[nj]);
            }
            __syncthreads();
        }

        // epilogue for this n-tile
#pragma unroll
        for (int mi = 0; mi < 2; mi++) {
            const size_t r0 = tok0 + wm + mi * 16 + lr;
#pragma unroll
            for (int nj = 0; nj < 4; nj++) {
                const int col = n0 + wn + nj * 8 + lc * 2;
                float2 b2 = *(const float2*)&bias[col];
                float2 v0 = make_float2(acc[mi][nj][0] + b2.x, acc[mi][nj][1] + b2.y);
                float2 v1 = make_float2(acc[mi][nj][2] + b2.x, acc[mi][nj][3] + b2.y);
                *(float2*)&out[r0 * D_ + col] = v0;
                *(float2*)&out[(r0 + 8) * D_ + col] = v1;
            }
        }
    }
}

// ---------------- launch ----------------
extern "C" void kernel_launch(void* const* d_in, const int* in_sizes, int n_in,
                              void* d_out, int out_size)
{
    const float* x     = (const float*)d_in[0];
    const float* Wqkv  = (const float*)d_in[1];
    const float* Wproj = (const float*)d_in[2];
    const float* bproj = (const float*)d_in[3];
    float* out = (float*)d_out;

    float *p_q, *p_xr, *p_wtq, *p_wtp;
    cudaGetSymbolAddress((void**)&p_q, g_q);
    cudaGetSymbolAddress((void**)&p_xr, g_xr);
    cudaGetSymbolAddress((void**)&p_wtq, g_Wtq);
    cudaGetSymbolAddress((void**)&p_wtp, g_Wtp);

    const int gemm_smem = (2 * BM_ * PADS_ + 2 * BN_ * PADS_) * 4;   // 73728
    const int kv_smem = KV_SMEM_FLOATS * 4;                          // 101376
    cudaFuncSetAttribute(gemm_mma<D_, D_, 0>, cudaFuncAttributeMaxDynamicSharedMemorySize, gemm_smem);
    cudaFuncSetAttribute(kv_ctx_kernel, cudaFuncAttributeMaxDynamicSharedMemorySize, kv_smem);
    cudaFuncSetAttribute(attn_proj_kernel, cudaFuncAttributeMaxDynamicSharedMemorySize, AP_SMEM_BYTES);

    // 0) prepasses
    {
        int n4 = TOK_ * D_ / 4;
        round_tf32_kernel<<<(n4 + 255) / 256, 256>>>((const float4*)x, (float4*)p_xr, n4);
    }
    transpose_kernel<<<dim3(3 * D_ / 32, D_ / 32), dim3(32, 8)>>>(Wqkv, p_wtq, D_, 3 * D_);
    transpose_kernel<<<dim3(D_ / 32, D_ / 32), dim3(32, 8)>>>(Wproj, p_wtp, D_, D_);
    zero_ctx_kernel<<<(B_ * H_ * C_ * C_ + 255) / 256, 256>>>();

    // 1) q = x @ Wq
    {
        dim3 grid(D_ / BN_, TOK_ / BM_);
        gemm_mma<D_, D_, 0><<<grid, 256, gemm_smem>>>(p_xr, p_wtq, nullptr, p_q);
    }

    // 2) fused kv-GEMM + context accumulation
    {
        dim3 grid(4, 256);
        kv_ctx_kernel<<<grid, 256, kv_smem>>>();
    }

    // 3) fused attn + proj
    {
        attn_proj_kernel<<<TOK_ / 64, 256, AP_SMEM_BYTES>>>(bproj, out);
    }
}

// round 8
// speedup vs baseline: 1.0161x; 1.0161x over previous
#include <cuda_runtime.h>
#include <math.h>
#include <stdint.h>

// Problem constants
#define B_      8
#define SEQ_    16384
#define D_      384
#define H_      8
#define C_      48
#define TOK_    (B_ * SEQ_)          // 131072

// ---------------- scratch (static device globals; no allocs allowed) ----------------
__device__ float g_q[(size_t)TOK_ * D_];           // 201 MB : q = x @ Wq
__device__ float g_attn[(size_t)TOK_ * D_];        // 201 MB : attention output (tf32-rounded)
__device__ float g_xr[(size_t)TOK_ * D_];          // 201 MB : x rounded to tf32
__device__ float g_ctx[B_ * H_ * C_ * C_];         // unnormalized k^T v context
__device__ float g_sum[B_ * H_ * C_];              // sum of exp(k) over tokens
__device__ float g_Wtq[3 * D_ * D_];               // W_qkv^T, tf32-rounded  [1152][384]
__device__ float g_Wtp[D_ * D_];                   // W_proj^T, tf32-rounded

__device__ __forceinline__ float f2tf32(float x) {
    uint32_t y;
    asm("cvt.rna.tf32.f32 %0, %1;" : "=r"(y) : "f"(x));
    return __uint_as_float(y);
}
__device__ __forceinline__ uint32_t smem_u32(const void* p) {
    uint32_t a;
    asm("{ .reg .u64 t; cvta.to.shared.u64 t, %1; cvt.u32.u64 %0, t; }" : "=r"(a) : "l"(p));
    return a;
}
__device__ __forceinline__ void cp_async16(uint32_t dst, const void* src) {
    asm volatile("cp.async.cg.shared.global [%0], [%1], 16;" :: "r"(dst), "l"(src));
}
__device__ __forceinline__ void mma_tf32(float* c, const uint32_t* a, const uint32_t* b) {
    asm volatile(
        "mma.sync.aligned.m16n8k8.row.col.f32.tf32.tf32.f32 "
        "{%0,%1,%2,%3}, {%4,%5,%6,%7}, {%8,%9}, {%0,%1,%2,%3};"
        : "+f"(c[0]), "+f"(c[1]), "+f"(c[2]), "+f"(c[3])
        : "r"(a[0]), "r"(a[1]), "r"(a[2]), "r"(a[3]), "r"(b[0]), "r"(b[1]));
}

// ---------------- zero the atomic accumulators (graph replays!) ----------------
__global__ void zero_ctx_kernel() {
    int i = blockIdx.x * 256 + threadIdx.x;
    if (i < B_ * H_ * C_ * C_) g_ctx[i] = 0.0f;
    if (i < B_ * H_ * C_)      g_sum[i] = 0.0f;
}

// ---------------- round x to tf32 (streaming) ----------------
__global__ void round_tf32_kernel(const float4* __restrict__ src, float4* __restrict__ dst, int n4) {
    int i = blockIdx.x * 256 + threadIdx.x;
    if (i < n4) {
        float4 v = src[i];
        v.x = f2tf32(v.x); v.y = f2tf32(v.y); v.z = f2tf32(v.z); v.w = f2tf32(v.w);
        dst[i] = v;
    }
}

// ---------------- weight transpose + tf32 round ----------------
__global__ void transpose_kernel(const float* __restrict__ src, float* __restrict__ dst,
                                 int R, int Ccols) {
    __shared__ float t[32][33];
    int bx = blockIdx.x * 32, by = blockIdx.y * 32;
    int tx = threadIdx.x, ty = threadIdx.y;
#pragma unroll
    for (int j = 0; j < 32; j += 8)
        t[ty + j][tx] = src[(size_t)(by + ty + j) * Ccols + bx + tx];
    __syncthreads();
#pragma unroll
    for (int j = 0; j < 32; j += 8)
        dst[(size_t)(bx + ty + j) * R + by + tx] = f2tf32(t[tx][ty + j]);
}

// ================= tf32 mma.sync GEMM (block 128x128, BK=32, 8 warps 2x4, warp 64x32) =================
#define BM_ 128
#define BN_ 128
#define BK_ 32
#define PADS_ 36

template <int K, int N, int HAS_BIAS>
__global__ void __launch_bounds__(256, 2)
gemm_mma(const float* __restrict__ A, const float* __restrict__ Bt,
         const float* __restrict__ bias, float* __restrict__ Cm)
{
    extern __shared__ float smem[];
    float* As = smem;
    float* Bs = smem + 2 * BM_ * PADS_;

    const int tid = threadIdx.x;
    const int wid = tid >> 5;
    const int lane = tid & 31;
    const int m0 = blockIdx.y * BM_;
    const int n0 = blockIdx.x * BN_;
    const int wm = (wid & 1) * 64;
    const int wn = (wid >> 1) * 32;
    const int lr = lane >> 2;
    const int lc = lane & 3;
    const int gr = tid >> 3;
    const int gc = (tid & 7) * 4;

    const uint32_t as_base = smem_u32(As);
    const uint32_t bs_base = smem_u32(Bs);

    float acc[4][4][4];
#pragma unroll
    for (int i = 0; i < 4; i++)
#pragma unroll
        for (int j = 0; j < 4; j++)
#pragma unroll
            for (int r = 0; r < 4; r++) acc[i][j][r] = 0.0f;

    constexpr int nch = K / BK_;

    {
#pragma unroll
        for (int i = 0; i < 4; i++) {
            int row = gr + i * 32;
            cp_async16(as_base + (row * PADS_ + gc) * 4, &A[(size_t)(m0 + row) * K + gc]);
            cp_async16(bs_base + (row * PADS_ + gc) * 4, &Bt[(size_t)(n0 + row) * K + gc]);
        }
        asm volatile("cp.async.commit_group;");
    }

#pragma unroll
    for (int c = 0; c < nch; c++) {
        asm volatile("cp.async.wait_group 0;");
        __syncthreads();

        if (c + 1 < nch) {
            const int k0 = (c + 1) * BK_;
            const int buf = (c + 1) & 1;
            const uint32_t ab = as_base + buf * BM_ * PADS_ * 4;
            const uint32_t bb = bs_base + buf * BN_ * PADS_ * 4;
#pragma unroll
            for (int i = 0; i < 4; i++) {
                int row = gr + i * 32;
                cp_async16(ab + (row * PADS_ + gc) * 4, &A[(size_t)(m0 + row) * K + k0 + gc]);
                cp_async16(bb + (row * PADS_ + gc) * 4, &Bt[(size_t)(n0 + row) * K + k0 + gc]);
            }
            asm volatile("cp.async.commit_group;");
        }

        const float* as = As + (c & 1) * BM_ * PADS_;
        const float* bs = Bs + (c & 1) * BN_ * PADS_;

#pragma unroll
        for (int ks = 0; ks < 4; ks++) {
            const int kk = ks * 8 + lc;
            uint32_t afr[4][4];
#pragma unroll
            for (int mi = 0; mi < 4; mi++) {
                int r = wm + mi * 16 + lr;
                afr[mi][0] = __float_as_uint(as[r * PADS_ + kk]);
                afr[mi][1] = __float_as_uint(as[(r + 8) * PADS_ + kk]);
                afr[mi][2] = __float_as_uint(as[r * PADS_ + kk + 4]);
                afr[mi][3] = __float_as_uint(as[(r + 8) * PADS_ + kk + 4]);
            }
            uint32_t bfr[4][2];
#pragma unroll
            for (int nj = 0; nj < 4; nj++) {
                int nn = wn + nj * 8 + lr;
                bfr[nj][0] = __float_as_uint(bs[nn * PADS_ + kk]);
                bfr[nj][1] = __float_as_uint(bs[nn * PADS_ + kk + 4]);
            }
#pragma unroll
            for (int mi = 0; mi < 4; mi++)
#pragma unroll
                for (int nj = 0; nj < 4; nj++)
                    mma_tf32(acc[mi][nj], afr[mi], bfr[nj]);
        }
        __syncthreads();
    }

#pragma unroll
    for (int mi = 0; mi < 4; mi++) {
        const int r0 = m0 + wm + mi * 16 + lr;
#pragma unroll
        for (int nj = 0; nj < 4; nj++) {
            const int col = n0 + wn + nj * 8 + lc * 2;
            float2 b2 = make_float2(0.f, 0.f);
            if (HAS_BIAS) b2 = *(const float2*)&bias[col];
            float2 v0 = make_float2(acc[mi][nj][0] + b2.x, acc[mi][nj][1] + b2.y);
            float2 v1 = make_float2(acc[mi][nj][2] + b2.x, acc[mi][nj][3] + b2.y);
            *(float2*)&Cm[(size_t)r0 * N + col] = v0;
            *(float2*)&Cm[(size_t)(r0 + 8) * N + col] = v1;
        }
    }
}

// ================= fused kv-GEMM + ctx kernel (R6) =================
#define KVN_ 192
#define ST_  132
#define KV_SMEM_FLOATS (2 * 96 * ST_)

__global__ void __launch_bounds__(256, 1)
kv_ctx_kernel()
{
    extern __shared__ float smem[];
    float* As = smem;
    float* Bs = smem + 2 * BM_ * PADS_;
    float* eT = smem;
    float* vT = smem + 96 * ST_;

    const int tid = threadIdx.x;
    const int wid = tid >> 5;
    const int lane = tid & 31;
    const int cg = blockIdx.x;
    const int ss = blockIdx.y;
    const int lr = lane >> 2;
    const int lc = lane & 3;
    const int wm = (wid & 1) * 64;
    const int wn = (wid >> 1) * 48;
    const int gr = tid >> 3;
    const int gc = (tid & 7) * 4;

    const uint32_t as_base = smem_u32(As);
    const uint32_t bs_base = smem_u32(Bs);

    const float* Wk = g_Wtq + (size_t)(D_ + cg * 96) * D_;
    const float* Wv = g_Wtq + (size_t)(2 * D_ + cg * 96) * D_;

    const int batch = ss / 32;

    float ctxa[5][4];
#pragma unroll
    for (int i = 0; i < 5; i++)
#pragma unroll
        for (int r = 0; r < 4; r++) ctxa[i][r] = 0.0f;
    float ssum = 0.0f;

    for (int rb = 0; rb < 4; rb++) {
        const size_t tok0 = ((size_t)ss * 4 + rb) * 128;
        const float* A = g_xr + tok0 * D_;

        float acc[4][6][4];
#pragma unroll
        for (int i = 0; i < 4; i++)
#pragma unroll
            for (int j = 0; j < 6; j++)
#pragma unroll
                for (int r = 0; r < 4; r++) acc[i][j][r] = 0.0f;

        {
#pragma unroll
            for (int i = 0; i < 4; i++) {
                int row = gr + i * 32;
                cp_async16(as_base + (row * PADS_ + gc) * 4, &A[(size_t)row * D_ + gc]);
            }
#pragma unroll
            for (int i = 0; i < 6; i++) {
                int row = gr + i * 32;
                const float* src = (row < 96) ? &Wk[(size_t)row * D_ + gc]
                                              : &Wv[(size_t)(row - 96) * D_ + gc];
                cp_async16(bs_base + (row * PADS_ + gc) * 4, src);
            }
            asm volatile("cp.async.commit_group;");
        }

#pragma unroll
        for (int c = 0; c < D_ / BK_; c++) {
            asm volatile("cp.async.wait_group 0;");
            __syncthreads();

            if (c + 1 < D_ / BK_) {
                const int k0 = (c + 1) * BK_;
                const int buf = (c + 1) & 1;
                const uint32_t ab = as_base + buf * BM_ * PADS_ * 4;
                const uint32_t bb = bs_base + buf * KVN_ * PADS_ * 4;
#pragma unroll
                for (int i = 0; i < 4; i++) {
                    int row = gr + i * 32;
                    cp_async16(ab + (row * PADS_ + gc) * 4, &A[(size_t)row * D_ + k0 + gc]);
                }
#pragma unroll
                for (int i = 0; i < 6; i++) {
                    int row = gr + i * 32;
                    const float* src = (row < 96) ? &Wk[(size_t)row * D_ + k0 + gc]
                                                  : &Wv[(size_t)(row - 96) * D_ + k0 + gc];
                    cp_async16(bb + (row * PADS_ + gc) * 4, src);
                }
                asm volatile("cp.async.commit_group;");
            }

            const float* as = As + (c & 1) * BM_ * PADS_;
            const float* bs = Bs + (c & 1) * KVN_ * PADS_;

#pragma unroll
            for (int ks = 0; ks < 4; ks++) {
                const int kk = ks * 8 + lc;
                uint32_t afr[4][4];
#pragma unroll
                for (int mi = 0; mi < 4; mi++) {
                    int r = wm + mi * 16 + lr;
                    afr[mi][0] = __float_as_uint(as[r * PADS_ + kk]);
                    afr[mi][1] = __float_as_uint(as[(r + 8) * PADS_ + kk]);
                    afr[mi][2] = __float_as_uint(as[r * PADS_ + kk + 4]);
                    afr[mi][3] = __float_as_uint(as[(r + 8) * PADS_ + kk + 4]);
                }
                uint32_t bfr[6][2];
#pragma unroll
                for (int nj = 0; nj < 6; nj++) {
                    int nn = wn + nj * 8 + lr;
                    bfr[nj][0] = __float_as_uint(bs[nn * PADS_ + kk]);
                    bfr[nj][1] = __float_as_uint(bs[nn * PADS_ + kk + 4]);
                }
#pragma unroll
                for (int mi = 0; mi < 4; mi++)
#pragma unroll
                    for (int nj = 0; nj < 6; nj++)
                        mma_tf32(acc[mi][nj], afr[mi], bfr[nj]);
            }
            __syncthreads();
        }

#pragma unroll
        for (int mi = 0; mi < 4; mi++) {
#pragma unroll
            for (int nj = 0; nj < 6; nj++) {
#pragma unroll
                for (int r = 0; r < 4; r++) {
                    int ch = wn + nj * 8 + lc * 2 + (r & 1);
                    int tl = wm + mi * 16 + lr + ((r >> 1) ? 8 : 0);
                    if (wid < 4) {
                        eT[ch * ST_ + tl] = f2tf32(__expf(acc[mi][nj][r]));
                    } else {
                        vT[(ch - 96) * ST_ + tl] = f2tf32(acc[mi][nj][r]);
                    }
                }
            }
        }
        __syncthreads();

#pragma unroll
        for (int i = 0; i < 5; i++) {
            int t = wid + 8 * i;
            if (t < 36) {
                int head = t / 18, rem = t % 18;
                int mi = rem / 6, nj = rem % 6;
                const float* ea = eT + (head * 48 + mi * 16) * ST_;
                const float* vb = vT + (head * 48 + nj * 8) * ST_;
#pragma unroll
                for (int ks = 0; ks < 16; ks++) {
                    const int kk = ks * 8 + lc;
                    uint32_t a[4], b[2];
                    a[0] = __float_as_uint(ea[lr * ST_ + kk]);
                    a[1] = __float_as_uint(ea[(lr + 8) * ST_ + kk]);
                    a[2] = __float_as_uint(ea[lr * ST_ + kk + 4]);
                    a[3] = __float_as_uint(ea[(lr + 8) * ST_ + kk + 4]);
                    b[0] = __float_as_uint(vb[lr * ST_ + kk]);
                    b[1] = __float_as_uint(vb[lr * ST_ + kk + 4]);
                    mma_tf32(ctxa[i], a, b);
                }
            }
        }

        if (tid < 96) {
            const float* row = eT + tid * ST_;
            float s = 0.0f;
#pragma unroll
            for (int j = 0; j < 32; j++) {
                float4 v = *(const float4*)&row[j * 4];
                s += (v.x + v.y) + (v.z + v.w);
            }
            ssum += s;
        }
        __syncthreads();
    }

#pragma unroll
    for (int i = 0; i < 5; i++) {
        int t = wid + 8 * i;
        if (t < 36) {
            int head = t / 18, rem = t % 18;
            int mi = rem / 6, nj = rem % 6;
            int bh = (batch * H_ + cg * 2 + head);
#pragma unroll
            for (int r = 0; r < 4; r++) {
                int c = mi * 16 + lr + ((r >> 1) ? 8 : 0);
                int d = nj * 8 + lc * 2 + (r & 1);
                atomicAdd(&g_ctx[((size_t)bh * C_ + c) * C_ + d], ctxa[i][r]);
            }
        }
    }
    if (tid < 96) {
        int head = tid / 48;
        atomicAdd(&g_sum[(batch * H_ + cg * 2 + head) * C_ + tid % 48], ssum);
    }
}

// ================= HMMA attn kernel: 64 tokens/CTA, warp h -> head h =================
#define AT_ST  388
#define CTX_ST 52
#define AN_AT_F    (64 * AT_ST)                 // 24832
#define AN_CTX_F   (H_ * C_ * CTX_ST)           // 19968
#define AN_SMEM_F  (AN_AT_F + AN_CTX_F + 512 + 384)
#define AN_SMEM_BYTES (AN_SMEM_F * 4)           // ~183 KB

__global__ void __launch_bounds__(256, 1)
attn_tc_kernel()
{
    extern __shared__ float smem[];
    float* at    = smem;                        // eq tile [64][AT_ST]
    float* ctxnT = smem + AN_AT_F;              // [8][48][CTX_ST]
    float* srow2 = ctxnT + AN_CTX_F;            // [64][8]
    float* sinv  = srow2 + 512;                 // [384]

    const int tid = threadIdx.x;
    const int wid = tid >> 5;
    const int lane = tid & 31;
    const int lr = lane >> 2;
    const int lc = lane & 3;
    const size_t tok0 = (size_t)blockIdx.x * 64;
    const int batch = blockIdx.x / (SEQ_ / 64);

    // ---- 1) at = tf32(exp(q)) ----
    {
        const float* qb = g_q + tok0 * D_;
        for (int idx = tid; idx < 64 * 96; idx += 256) {
            int r = idx / 96, c4 = idx % 96;
            float4 v = *(const float4*)&qb[(size_t)r * D_ + c4 * 4];
            v.x = f2tf32(__expf(v.x)); v.y = f2tf32(__expf(v.y));
            v.z = f2tf32(__expf(v.z)); v.w = f2tf32(__expf(v.w));
            *(float4*)&at[r * AT_ST + c4 * 4] = v;
        }
    }
    for (int idx = tid; idx < H_ * C_; idx += 256)
        sinv[idx] = 1.0f / g_sum[batch * (H_ * C_) + idx];
    __syncthreads();

    // ---- 2) ctxnT[h][d][c] = tf32(ctx[h][c][d] * sinv[h][c]) ----
    {
        const float* cb = g_ctx + (size_t)batch * (H_ * C_ * C_);
        for (int idx = tid; idx < H_ * C_ * C_; idx += 256) {
            int h = idx / (C_ * C_), rem = idx % (C_ * C_);
            int c = rem / C_, d = rem % C_;
            ctxnT[h * (C_ * CTX_ST) + d * CTX_ST + c] =
                f2tf32(cb[h * (C_ * C_) + c * C_ + d] * sinv[h * C_ + c]);
        }
    }
    __syncthreads();
    for (int p = tid; p < 512; p += 256) {
        int r = p >> 3, h = p & 7;
        const float* rowp = at + r * AT_ST + h * C_;
        float s = 0.0f;
#pragma unroll
        for (int c = 0; c < C_; c++) s += rowp[c];
        srow2[p] = 1.0f / s;
    }
    __syncthreads();

    // ---- 3) warp h: attn[64x48] = eq_h @ ctxnT_h, scale, write to g_attn ----
    {
        const int h = wid;
        const float* Ah = at + h * C_;
        const float* Bh = ctxnT + h * (C_ * CTX_ST);
        float acc[4][6][4];
#pragma unroll
        for (int i = 0; i < 4; i++)
#pragma unroll
            for (int j = 0; j < 6; j++)
#pragma unroll
                for (int r = 0; r < 4; r++) acc[i][j][r] = 0.0f;

#pragma unroll
        for (int ks = 0; ks < 6; ks++) {
            const int kk = ks * 8 + lc;
            uint32_t afr[4][4];
#pragma unroll
            for (int mi = 0; mi < 4; mi++) {
                int r = mi * 16 + lr;
                afr[mi][0] = __float_as_uint(Ah[r * AT_ST + kk]);
                afr[mi][1] = __float_as_uint(Ah[(r + 8) * AT_ST + kk]);
                afr[mi][2] = __float_as_uint(Ah[r * AT_ST + kk + 4]);
                afr[mi][3] = __float_as_uint(Ah[(r + 8) * AT_ST + kk + 4]);
            }
            uint32_t bfr[6][2];
#pragma unroll
            for (int nj = 0; nj < 6; nj++) {
                int nn = nj * 8 + lr;
                bfr[nj][0] = __float_as_uint(Bh[nn * CTX_ST + kk]);
                bfr[nj][1] = __float_as_uint(Bh[nn * CTX_ST + kk + 4]);
            }
#pragma unroll
            for (int mi = 0; mi < 4; mi++)
#pragma unroll
                for (int nj = 0; nj < 6; nj++)
                    mma_tf32(acc[mi][nj], afr[mi], bfr[nj]);
        }

        float* ob = g_attn + tok0 * D_;
#pragma unroll
        for (int mi = 0; mi < 4; mi++) {
            const int ra = mi * 16 + lr;
            const float sa = srow2[ra * 8 + h];
            const float sb = srow2[(ra + 8) * 8 + h];
#pragma unroll
            for (int nj = 0; nj < 6; nj++) {
                const int col = h * C_ + nj * 8 + lc * 2;
                float2 v0 = make_float2(f2tf32(acc[mi][nj][0] * sa), f2tf32(acc[mi][nj][1] * sa));
                float2 v1 = make_float2(f2tf32(acc[mi][nj][2] * sb), f2tf32(acc[mi][nj][3] * sb));
                *(float2*)&ob[(size_t)ra * D_ + col] = v0;
                *(float2*)&ob[(size_t)(ra + 8) * D_ + col] = v1;
            }
        }
    }
}

// ---------------- launch ----------------
extern "C" void kernel_launch(void* const* d_in, const int* in_sizes, int n_in,
                              void* d_out, int out_size)
{
    const float* x     = (const float*)d_in[0];
    const float* Wqkv  = (const float*)d_in[1];
    const float* Wproj = (const float*)d_in[2];
    const float* bproj = (const float*)d_in[3];
    float* out = (float*)d_out;

    float *p_q, *p_attn, *p_xr, *p_wtq, *p_wtp;
    cudaGetSymbolAddress((void**)&p_q, g_q);
    cudaGetSymbolAddress((void**)&p_attn, g_attn);
    cudaGetSymbolAddress((void**)&p_xr, g_xr);
    cudaGetSymbolAddress((void**)&p_wtq, g_Wtq);
    cudaGetSymbolAddress((void**)&p_wtp, g_Wtp);

    const int gemm_smem = (2 * BM_ * PADS_ + 2 * BN_ * PADS_) * 4;   // 73728
    const int kv_smem = KV_SMEM_FLOATS * 4;                          // 101376
    cudaFuncSetAttribute(gemm_mma<D_, D_, 0>, cudaFuncAttributeMaxDynamicSharedMemorySize, gemm_smem);
    cudaFuncSetAttribute(gemm_mma<D_, D_, 1>, cudaFuncAttributeMaxDynamicSharedMemorySize, gemm_smem);
    cudaFuncSetAttribute(kv_ctx_kernel, cudaFuncAttributeMaxDynamicSharedMemorySize, kv_smem);
    cudaFuncSetAttribute(attn_tc_kernel, cudaFuncAttributeMaxDynamicSharedMemorySize, AN_SMEM_BYTES);

    // 0) prepasses
    {
        int n4 = TOK_ * D_ / 4;
        round_tf32_kernel<<<(n4 + 255) / 256, 256>>>((const float4*)x, (float4*)p_xr, n4);
    }
    transpose_kernel<<<dim3(3 * D_ / 32, D_ / 32), dim3(32, 8)>>>(Wqkv, p_wtq, D_, 3 * D_);
    transpose_kernel<<<dim3(D_ / 32, D_ / 32), dim3(32, 8)>>>(Wproj, p_wtp, D_, D_);
    zero_ctx_kernel<<<(B_ * H_ * C_ * C_ + 255) / 256, 256>>>();

    // 1) q = x @ Wq
    {
        dim3 grid(D_ / BN_, TOK_ / BM_);
        gemm_mma<D_, D_, 0><<<grid, 256, gemm_smem>>>(p_xr, p_wtq, nullptr, p_q);
    }

    // 2) fused kv-GEMM + context accumulation
    {
        dim3 grid(4, 256);
        kv_ctx_kernel<<<grid, 256, kv_smem>>>();
    }

    // 3) HMMA attn (writes tf32-rounded g_attn)
    {
        attn_tc_kernel<<<TOK_ / 64, 256, AN_SMEM_BYTES>>>();
    }

    // 4) out = attn @ W_proj + b_proj
    {
        dim3 grid(D_ / BN_, TOK_ / BM_);
        gemm_mma<D_, D_, 1><<<grid, 256, gemm_smem>>>(p_attn, p_wtp, bproj, out);
    }
}

// round 9
// speedup vs baseline: 1.0966x; 1.0793x over previous
#include <cuda_runtime.h>
#include <math.h>
#include <stdint.h>

// Problem constants
#define B_      8
#define SEQ_    16384
#define D_      384
#define H_      8
#define C_      48
#define TOK_    (B_ * SEQ_)          // 131072

#define ACT_ST  52                   // padded row stride for ctxnT / eq tiles

// ---------------- scratch (static device globals; no allocs allowed) ----------------
__device__ float g_q[(size_t)TOK_ * D_];           // 201 MB : q = x @ Wq
__device__ float g_attn[(size_t)TOK_ * D_];        // 201 MB : attention output (tf32-rounded)
__device__ float g_xr[(size_t)TOK_ * D_];          // 201 MB : x rounded to tf32
__device__ float g_ctx[B_ * H_ * C_ * C_];         // unnormalized k^T v context
__device__ float g_sum[B_ * H_ * C_];              // sum of exp(k) over tokens
__device__ float g_ctxnT[B_ * H_ * C_ * ACT_ST];   // normalized, transposed, tf32, padded
__device__ float g_Wtq[3 * D_ * D_];               // W_qkv^T, tf32-rounded  [1152][384]
__device__ float g_Wtp[D_ * D_];                   // W_proj^T, tf32-rounded

__device__ __forceinline__ float f2tf32(float x) {
    uint32_t y;
    asm("cvt.rna.tf32.f32 %0, %1;" : "=r"(y) : "f"(x));
    return __uint_as_float(y);
}
__device__ __forceinline__ uint32_t smem_u32(const void* p) {
    uint32_t a;
    asm("{ .reg .u64 t; cvta.to.shared.u64 t, %1; cvt.u32.u64 %0, t; }" : "=r"(a) : "l"(p));
    return a;
}
__device__ __forceinline__ void cp_async16(uint32_t dst, const void* src) {
    asm volatile("cp.async.cg.shared.global [%0], [%1], 16;" :: "r"(dst), "l"(src));
}
__device__ __forceinline__ void mma_tf32(float* c, const uint32_t* a, const uint32_t* b) {
    asm volatile(
        "mma.sync.aligned.m16n8k8.row.col.f32.tf32.tf32.f32 "
        "{%0,%1,%2,%3}, {%4,%5,%6,%7}, {%8,%9}, {%0,%1,%2,%3};"
        : "+f"(c[0]), "+f"(c[1]), "+f"(c[2]), "+f"(c[3])
        : "r"(a[0]), "r"(a[1]), "r"(a[2]), "r"(a[3]), "r"(b[0]), "r"(b[1]));
}

// ---------------- zero the atomic accumulators (graph replays!) ----------------
__global__ void zero_ctx_kernel() {
    int i = blockIdx.x * 256 + threadIdx.x;
    if (i < B_ * H_ * C_ * C_) g_ctx[i] = 0.0f;
    if (i < B_ * H_ * C_)      g_sum[i] = 0.0f;
}

// ---------------- round x to tf32 (streaming) ----------------
__global__ void round_tf32_kernel(const float4* __restrict__ src, float4* __restrict__ dst, int n4) {
    int i = blockIdx.x * 256 + threadIdx.x;
    if (i < n4) {
        float4 v = src[i];
        v.x = f2tf32(v.x); v.y = f2tf32(v.y); v.z = f2tf32(v.z); v.w = f2tf32(v.w);
        dst[i] = v;
    }
}

// ---------------- weight transpose + tf32 round ----------------
__global__ void transpose_kernel(const float* __restrict__ src, float* __restrict__ dst,
                                 int R, int Ccols) {
    __shared__ float t[32][33];
    int bx = blockIdx.x * 32, by = blockIdx.y * 32;
    int tx = threadIdx.x, ty = threadIdx.y;
#pragma unroll
    for (int j = 0; j < 32; j += 8)
        t[ty + j][tx] = src[(size_t)(by + ty + j) * Ccols + bx + tx];
    __syncthreads();
#pragma unroll
    for (int j = 0; j < 32; j += 8)
        dst[(size_t)(bx + ty + j) * R + by + tx] = f2tf32(t[tx][ty + j]);
}

// ================= tf32 mma.sync GEMM (block 128x128, BK=32, 8 warps 2x4, warp 64x32) =================
#define BM_ 128
#define BN_ 128
#define BK_ 32
#define PADS_ 36

template <int K, int N, int HAS_BIAS>
__global__ void __launch_bounds__(256, 2)
gemm_mma(const float* __restrict__ A, const float* __restrict__ Bt,
         const float* __restrict__ bias, float* __restrict__ Cm)
{
    extern __shared__ float smem[];
    float* As = smem;
    float* Bs = smem + 2 * BM_ * PADS_;

    const int tid = threadIdx.x;
    const int wid = tid >> 5;
    const int lane = tid & 31;
    const int m0 = blockIdx.y * BM_;
    const int n0 = blockIdx.x * BN_;
    const int wm = (wid & 1) * 64;
    const int wn = (wid >> 1) * 32;
    const int lr = lane >> 2;
    const int lc = lane & 3;
    const int gr = tid >> 3;
    const int gc = (tid & 7) * 4;

    const uint32_t as_base = smem_u32(As);
    const uint32_t bs_base = smem_u32(Bs);

    float acc[4][4][4];
#pragma unroll
    for (int i = 0; i < 4; i++)
#pragma unroll
        for (int j = 0; j < 4; j++)
#pragma unroll
            for (int r = 0; r < 4; r++) acc[i][j][r] = 0.0f;

    constexpr int nch = K / BK_;

    {
#pragma unroll
        for (int i = 0; i < 4; i++) {
            int row = gr + i * 32;
            cp_async16(as_base + (row * PADS_ + gc) * 4, &A[(size_t)(m0 + row) * K + gc]);
            cp_async16(bs_base + (row * PADS_ + gc) * 4, &Bt[(size_t)(n0 + row) * K + gc]);
        }
        asm volatile("cp.async.commit_group;");
    }

#pragma unroll
    for (int c = 0; c < nch; c++) {
        asm volatile("cp.async.wait_group 0;");
        __syncthreads();

        if (c + 1 < nch) {
            const int k0 = (c + 1) * BK_;
            const int buf = (c + 1) & 1;
            const uint32_t ab = as_base + buf * BM_ * PADS_ * 4;
            const uint32_t bb = bs_base + buf * BN_ * PADS_ * 4;
#pragma unroll
            for (int i = 0; i < 4; i++) {
                int row = gr + i * 32;
                cp_async16(ab + (row * PADS_ + gc) * 4, &A[(size_t)(m0 + row) * K + k0 + gc]);
                cp_async16(bb + (row * PADS_ + gc) * 4, &Bt[(size_t)(n0 + row) * K + k0 + gc]);
            }
            asm volatile("cp.async.commit_group;");
        }

        const float* as = As + (c & 1) * BM_ * PADS_;
        const float* bs = Bs + (c & 1) * BN_ * PADS_;

#pragma unroll
        for (int ks = 0; ks < 4; ks++) {
            const int kk = ks * 8 + lc;
            uint32_t afr[4][4];
#pragma unroll
            for (int mi = 0; mi < 4; mi++) {
                int r = wm + mi * 16 + lr;
                afr[mi][0] = __float_as_uint(as[r * PADS_ + kk]);
                afr[mi][1] = __float_as_uint(as[(r + 8) * PADS_ + kk]);
                afr[mi][2] = __float_as_uint(as[r * PADS_ + kk + 4]);
                afr[mi][3] = __float_as_uint(as[(r + 8) * PADS_ + kk + 4]);
            }
            uint32_t bfr[4][2];
#pragma unroll
            for (int nj = 0; nj < 4; nj++) {
                int nn = wn + nj * 8 + lr;
                bfr[nj][0] = __float_as_uint(bs[nn * PADS_ + kk]);
                bfr[nj][1] = __float_as_uint(bs[nn * PADS_ + kk + 4]);
            }
#pragma unroll
            for (int mi = 0; mi < 4; mi++)
#pragma unroll
                for (int nj = 0; nj < 4; nj++)
                    mma_tf32(acc[mi][nj], afr[mi], bfr[nj]);
        }
        __syncthreads();
    }

#pragma unroll
    for (int mi = 0; mi < 4; mi++) {
        const int r0 = m0 + wm + mi * 16 + lr;
#pragma unroll
        for (int nj = 0; nj < 4; nj++) {
            const int col = n0 + wn + nj * 8 + lc * 2;
            float2 b2 = make_float2(0.f, 0.f);
            if (HAS_BIAS) b2 = *(const float2*)&bias[col];
            float2 v0 = make_float2(acc[mi][nj][0] + b2.x, acc[mi][nj][1] + b2.y);
            float2 v1 = make_float2(acc[mi][nj][2] + b2.x, acc[mi][nj][3] + b2.y);
            *(float2*)&Cm[(size_t)r0 * N + col] = v0;
            *(float2*)&Cm[(size_t)(r0 + 8) * N + col] = v1;
        }
    }
}

// ================= fused kv-GEMM + ctx kernel (R6) =================
#define KVN_ 192
#define ST_  132
#define KV_SMEM_FLOATS (2 * 96 * ST_)

__global__ void __launch_bounds__(256, 1)
kv_ctx_kernel()
{
    extern __shared__ float smem[];
    float* As = smem;
    float* Bs = smem + 2 * BM_ * PADS_;
    float* eT = smem;
    float* vT = smem + 96 * ST_;

    const int tid = threadIdx.x;
    const int wid = tid >> 5;
    const int lane = tid & 31;
    const int cg = blockIdx.x;
    const int ss = blockIdx.y;
    const int lr = lane >> 2;
    const int lc = lane & 3;
    const int wm = (wid & 1) * 64;
    const int wn = (wid >> 1) * 48;
    const int gr = tid >> 3;
    const int gc = (tid & 7) * 4;

    const uint32_t as_base = smem_u32(As);
    const uint32_t bs_base = smem_u32(Bs);

    const float* Wk = g_Wtq + (size_t)(D_ + cg * 96) * D_;
    const float* Wv = g_Wtq + (size_t)(2 * D_ + cg * 96) * D_;

    const int batch = ss / 32;

    float ctxa[5][4];
#pragma unroll
    for (int i = 0; i < 5; i++)
#pragma unroll
        for (int r = 0; r < 4; r++) ctxa[i][r] = 0.0f;
    float ssum = 0.0f;

    for (int rb = 0; rb < 4; rb++) {
        const size_t tok0 = ((size_t)ss * 4 + rb) * 128;
        const float* A = g_xr + tok0 * D_;

        float acc[4][6][4];
#pragma unroll
        for (int i = 0; i < 4; i++)
#pragma unroll
            for (int j = 0; j < 6; j++)
#pragma unroll
                for (int r = 0; r < 4; r++) acc[i][j][r] = 0.0f;

        {
#pragma unroll
            for (int i = 0; i < 4; i++) {
                int row = gr + i * 32;
                cp_async16(as_base + (row * PADS_ + gc) * 4, &A[(size_t)row * D_ + gc]);
            }
#pragma unroll
            for (int i = 0; i < 6; i++) {
                int row = gr + i * 32;
                const float* src = (row < 96) ? &Wk[(size_t)row * D_ + gc]
                                              : &Wv[(size_t)(row - 96) * D_ + gc];
                cp_async16(bs_base + (row * PADS_ + gc) * 4, src);
            }
            asm volatile("cp.async.commit_group;");
        }

#pragma unroll
        for (int c = 0; c < D_ / BK_; c++) {
            asm volatile("cp.async.wait_group 0;");
            __syncthreads();

            if (c + 1 < D_ / BK_) {
                const int k0 = (c + 1) * BK_;
                const int buf = (c + 1) & 1;
                const uint32_t ab = as_base + buf * BM_ * PADS_ * 4;
                const uint32_t bb = bs_base + buf * KVN_ * PADS_ * 4;
#pragma unroll
                for (int i = 0; i < 4; i++) {
                    int row = gr + i * 32;
                    cp_async16(ab + (row * PADS_ + gc) * 4, &A[(size_t)row * D_ + k0 + gc]);
                }
#pragma unroll
                for (int i = 0; i < 6; i++) {
                    int row = gr + i * 32;
                    const float* src = (row < 96) ? &Wk[(size_t)row * D_ + k0 + gc]
                                                  : &Wv[(size_t)(row - 96) * D_ + k0 + gc];
                    cp_async16(bb + (row * PADS_ + gc) * 4, src);
                }
                asm volatile("cp.async.commit_group;");
            }

            const float* as = As + (c & 1) * BM_ * PADS_;
            const float* bs = Bs + (c & 1) * KVN_ * PADS_;

#pragma unroll
            for (int ks = 0; ks < 4; ks++) {
                const int kk = ks * 8 + lc;
                uint32_t afr[4][4];
#pragma unroll
                for (int mi = 0; mi < 4; mi++) {
                    int r = wm + mi * 16 + lr;
                    afr[mi][0] = __float_as_uint(as[r * PADS_ + kk]);
                    afr[mi][1] = __float_as_uint(as[(r + 8) * PADS_ + kk]);
                    afr[mi][2] = __float_as_uint(as[r * PADS_ + kk + 4]);
                    afr[mi][3] = __float_as_uint(as[(r + 8) * PADS_ + kk + 4]);
                }
                uint32_t bfr[6][2];
#pragma unroll
                for (int nj = 0; nj < 6; nj++) {
                    int nn = wn + nj * 8 + lr;
                    bfr[nj][0] = __float_as_uint(bs[nn * PADS_ + kk]);
                    bfr[nj][1] = __float_as_uint(bs[nn * PADS_ + kk + 4]);
                }
#pragma unroll
                for (int mi = 0; mi < 4; mi++)
#pragma unroll
                    for (int nj = 0; nj < 6; nj++)
                        mma_tf32(acc[mi][nj], afr[mi], bfr[nj]);
            }
            __syncthreads();
        }

#pragma unroll
        for (int mi = 0; mi < 4; mi++) {
#pragma unroll
            for (int nj = 0; nj < 6; nj++) {
#pragma unroll
                for (int r = 0; r < 4; r++) {
                    int ch = wn + nj * 8 + lc * 2 + (r & 1);
                    int tl = wm + mi * 16 + lr + ((r >> 1) ? 8 : 0);
                    if (wid < 4) {
                        eT[ch * ST_ + tl] = f2tf32(__expf(acc[mi][nj][r]));
                    } else {
                        vT[(ch - 96) * ST_ + tl] = f2tf32(acc[mi][nj][r]);
                    }
                }
            }
        }
        __syncthreads();

#pragma unroll
        for (int i = 0; i < 5; i++) {
            int t = wid + 8 * i;
            if (t < 36) {
                int head = t / 18, rem = t % 18;
                int mi = rem / 6, nj = rem % 6;
                const float* ea = eT + (head * 48 + mi * 16) * ST_;
                const float* vb = vT + (head * 48 + nj * 8) * ST_;
#pragma unroll
                for (int ks = 0; ks < 16; ks++) {
                    const int kk = ks * 8 + lc;
                    uint32_t a[4], b[2];
                    a[0] = __float_as_uint(ea[lr * ST_ + kk]);
                    a[1] = __float_as_uint(ea[(lr + 8) * ST_ + kk]);
                    a[2] = __float_as_uint(ea[lr * ST_ + kk + 4]);
                    a[3] = __float_as_uint(ea[(lr + 8) * ST_ + kk + 4]);
                    b[0] = __float_as_uint(vb[lr * ST_ + kk]);
                    b[1] = __float_as_uint(vb[lr * ST_ + kk + 4]);
                    mma_tf32(ctxa[i], a, b);
                }
            }
        }

        if (tid < 96) {
            const float* row = eT + tid * ST_;
            float s = 0.0f;
#pragma unroll
            for (int j = 0; j < 32; j++) {
                float4 v = *(const float4*)&row[j * 4];
                s += (v.x + v.y) + (v.z + v.w);
            }
            ssum += s;
        }
        __syncthreads();
    }

#pragma unroll
    for (int i = 0; i < 5; i++) {
        int t = wid + 8 * i;
        if (t < 36) {
            int head = t / 18, rem = t % 18;
            int mi = rem / 6, nj = rem % 6;
            int bh = (batch * H_ + cg * 2 + head);
#pragma unroll
            for (int r = 0; r < 4; r++) {
                int c = mi * 16 + lr + ((r >> 1) ? 8 : 0);
                int d = nj * 8 + lc * 2 + (r & 1);
                atomicAdd(&g_ctx[((size_t)bh * C_ + c) * C_ + d], ctxa[i][r]);
            }
        }
    }
    if (tid < 96) {
        int head = tid / 48;
        atomicAdd(&g_sum[(batch * H_ + cg * 2 + head) * C_ + tid % 48], ssum);
    }
}

// ================= global context normalization (one-shot) =================
// ctxnT[bh][d][c] = tf32(ctx[bh][c][d] / sum[bh][c]); padded row stride ACT_ST.
__global__ void ctxn_norm_kernel()
{
    __shared__ float sinv[C_];
    const int bh = blockIdx.x;
    if (threadIdx.x < C_) sinv[threadIdx.x] = 1.0f / g_sum[bh * C_ + threadIdx.x];
    __syncthreads();
    const float* cb = g_ctx + (size_t)bh * (C_ * C_);
    float* ob = g_ctxnT + (size_t)bh * (C_ * ACT_ST);
    for (int i = threadIdx.x; i < C_ * C_; i += 256) {
        int c = i / C_, d = i % C_;
        ob[d * ACT_ST + c] = f2tf32(cb[i] * sinv[c]);
    }
}

// ================= HMMA attn: CTA = 128 tokens x 1 head, 128 threads =================
__global__ void __launch_bounds__(128, 4)
attn_tc_kernel()
{
    __shared__ float eq[128 * ACT_ST];      // 26624 B
    __shared__ float ctxT[C_ * ACT_ST];     // 9984 B
    __shared__ float srow[128];

    const int tid = threadIdx.x;
    const int wid = tid >> 5;
    const int lane = tid & 31;
    const int lr = lane >> 2;
    const int lc = lane & 3;
    const int h = blockIdx.x & 7;
    const size_t tok0 = (size_t)(blockIdx.x >> 3) * 128;
    const int batch = (int)(tok0 / SEQ_);

    // ---- fill ctxT (precomputed, L2-resident) ----
    {
        const float4* src = (const float4*)(g_ctxnT + ((size_t)batch * H_ + h) * (C_ * ACT_ST));
        float4* dst = (float4*)ctxT;
#pragma unroll
        for (int i = tid; i < C_ * ACT_ST / 4; i += 128) dst[i] = src[i];
    }
    // ---- fill eq = tf32(exp(q[:, h*48 : h*48+48])) ----
    {
        const float* qb = g_q + tok0 * D_ + h * C_;
        for (int i = tid; i < 128 * 12; i += 128) {
            int r = i / 12, c4 = i % 12;
            float4 v = *(const float4*)&qb[(size_t)r * D_ + c4 * 4];
            v.x = f2tf32(__expf(v.x)); v.y = f2tf32(__expf(v.y));
            v.z = f2tf32(__expf(v.z)); v.w = f2tf32(__expf(v.w));
            *(float4*)&eq[r * ACT_ST + c4 * 4] = v;
        }
    }
    __syncthreads();
    // ---- row sums ----
    {
        const float* rp = eq + tid * ACT_ST;
        float s = 0.0f;
#pragma unroll
        for (int j = 0; j < 12; j++) {
            float4 v = *(const float4*)&rp[j * 4];
            s += (v.x + v.y) + (v.z + v.w);
        }
        srow[tid] = 1.0f / s;
    }
    __syncthreads();

    // ---- warp w: rows w*32..w*32+31 ; attn = eq @ ctxT^T ----
    float acc[2][6][4];
#pragma unroll
    for (int i = 0; i < 2; i++)
#pragma unroll
        for (int j = 0; j < 6; j++)
#pragma unroll
            for (int r = 0; r < 4; r++) acc[i][j][r] = 0.0f;

    const float* Ah = eq + wid * 32 * ACT_ST;
#pragma unroll
    for (int ks = 0; ks < 6; ks++) {
        const int kk = ks * 8 + lc;
        uint32_t afr[2][4];
#pragma unroll
        for (int mi = 0; mi < 2; mi++) {
            int r = mi * 16 + lr;
            afr[mi][0] = __float_as_uint(Ah[r * ACT_ST + kk]);
            afr[mi][1] = __float_as_uint(Ah[(r + 8) * ACT_ST + kk]);
            afr[mi][2] = __float_as_uint(Ah[r * ACT_ST + kk + 4]);
            afr[mi][3] = __float_as_uint(Ah[(r + 8) * ACT_ST + kk + 4]);
        }
        uint32_t bfr[6][2];
#pragma unroll
        for (int nj = 0; nj < 6; nj++) {
            int nn = nj * 8 + lr;
            bfr[nj][0] = __float_as_uint(ctxT[nn * ACT_ST + kk]);
            bfr[nj][1] = __float_as_uint(ctxT[nn * ACT_ST + kk + 4]);
        }
#pragma unroll
        for (int mi = 0; mi < 2; mi++)
#pragma unroll
            for (int nj = 0; nj < 6; nj++)
                mma_tf32(acc[mi][nj], afr[mi], bfr[nj]);
    }

    // ---- scale + write (tf32-rounded for proj) ----
    float* ob = g_attn + tok0 * D_ + h * C_;
#pragma unroll
    for (int mi = 0; mi < 2; mi++) {
        const int ra = wid * 32 + mi * 16 + lr;
        const float sa = srow[ra];
        const float sb = srow[ra + 8];
#pragma unroll
        for (int nj = 0; nj < 6; nj++) {
            const int col = nj * 8 + lc * 2;
            float2 v0 = make_float2(f2tf32(acc[mi][nj][0] * sa), f2tf32(acc[mi][nj][1] * sa));
            float2 v1 = make_float2(f2tf32(acc[mi][nj][2] * sb), f2tf32(acc[mi][nj][3] * sb));
            *(float2*)&ob[(size_t)ra * D_ + col] = v0;
            *(float2*)&ob[(size_t)(ra + 8) * D_ + col] = v1;
        }
    }
}

// ---------------- launch ----------------
extern "C" void kernel_launch(void* const* d_in, const int* in_sizes, int n_in,
                              void* d_out, int out_size)
{
    const float* x     = (const float*)d_in[0];
    const float* Wqkv  = (const float*)d_in[1];
    const float* Wproj = (const float*)d_in[2];
    const float* bproj = (const float*)d_in[3];
    float* out = (float*)d_out;

    float *p_q, *p_attn, *p_xr, *p_wtq, *p_wtp;
    cudaGetSymbolAddress((void**)&p_q, g_q);
    cudaGetSymbolAddress((void**)&p_attn, g_attn);
    cudaGetSymbolAddress((void**)&p_xr, g_xr);
    cudaGetSymbolAddress((void**)&p_wtq, g_Wtq);
    cudaGetSymbolAddress((void**)&p_wtp, g_Wtp);

    const int gemm_smem = (2 * BM_ * PADS_ + 2 * BN_ * PADS_) * 4;   // 73728
    const int kv_smem = KV_SMEM_FLOATS * 4;                          // 101376
    cudaFuncSetAttribute(gemm_mma<D_, D_, 0>, cudaFuncAttributeMaxDynamicSharedMemorySize, gemm_smem);
    cudaFuncSetAttribute(gemm_mma<D_, D_, 1>, cudaFuncAttributeMaxDynamicSharedMemorySize, gemm_smem);
    cudaFuncSetAttribute(kv_ctx_kernel, cudaFuncAttributeMaxDynamicSharedMemorySize, kv_smem);

    // 0) prepasses
    {
        int n4 = TOK_ * D_ / 4;
        round_tf32_kernel<<<(n4 + 255) / 256, 256>>>((const float4*)x, (float4*)p_xr, n4);
    }
    transpose_kernel<<<dim3(3 * D_ / 32, D_ / 32), dim3(32, 8)>>>(Wqkv, p_wtq, D_, 3 * D_);
    transpose_kernel<<<dim3(D_ / 32, D_ / 32), dim3(32, 8)>>>(Wproj, p_wtp, D_, D_);
    zero_ctx_kernel<<<(B_ * H_ * C_ * C_ + 255) / 256, 256>>>();

    // 1) q = x @ Wq
    {
        dim3 grid(D_ / BN_, TOK_ / BM_);
        gemm_mma<D_, D_, 0><<<grid, 256, gemm_smem>>>(p_xr, p_wtq, nullptr, p_q);
    }

    // 2) fused kv-GEMM + context accumulation
    {
        dim3 grid(4, 256);
        kv_ctx_kernel<<<grid, 256, kv_smem>>>();
    }

    // 3) one-shot context normalization (tiny)
    ctxn_norm_kernel<<<B_ * H_, 256>>>();

    // 4) HMMA attn (writes tf32-rounded g_attn)
    attn_tc_kernel<<<(TOK_ / 128) * H_, 128>>>();

    // 5) out = attn @ W_proj + b_proj
    {
        dim3 grid(D_ / BN_, TOK_ / BM_);
        gemm_mma<D_, D_, 1><<<grid, 256, gemm_smem>>>(p_attn, p_wtp, bproj, out);
    }
}

// round 10
// speedup vs baseline: 1.7071x; 1.5567x over previous
#include <cuda_runtime.h>
#include <cuda_fp16.h>
#include <math.h>
#include <stdint.h>

// Problem constants
#define B_      8
#define SEQ_    16384
#define D_      384
#define H_      8
#define C_      48
#define TOK_    (B_ * SEQ_)          // 131072

// ---------------- scratch (static device globals; no allocs allowed) ----------------
__device__ float  g_q[(size_t)TOK_ * D_];            // 201 MB : q = x @ Wq (fp32)
__device__ __half g_attnh[(size_t)TOK_ * D_];        // 100 MB : attention output (fp16)
__device__ __half g_xh[(size_t)TOK_ * D_];           // 100 MB : x rounded to fp16
__device__ float  g_ctx[B_ * H_ * C_ * C_];          // unnormalized k^T v context
__device__ float  g_sum[B_ * H_ * C_];               // sum of exp(k) over tokens
__device__ __half g_ctxnTh[B_ * H_ * C_ * 56];       // normalized, transposed, fp16, padded
__device__ __half g_Wtqh[3 * D_ * D_];               // W_qkv^T, fp16  [1152][384]
__device__ __half g_Wtph[D_ * D_];                   // W_proj^T, fp16

__device__ __forceinline__ uint32_t smem_u32(const void* p) {
    uint32_t a;
    asm("{ .reg .u64 t; cvta.to.shared.u64 t, %1; cvt.u32.u64 %0, t; }" : "=r"(a) : "l"(p));
    return a;
}
__device__ __forceinline__ void cp_async16(uint32_t dst, const void* src) {
    asm volatile("cp.async.cg.shared.global [%0], [%1], 16;" :: "r"(dst), "l"(src));
}
__device__ __forceinline__ void mma_f16(float* c, const uint32_t* a, const uint32_t* b) {
    asm volatile(
        "mma.sync.aligned.m16n8k16.row.col.f32.f16.f16.f32 "
        "{%0,%1,%2,%3}, {%4,%5,%6,%7}, {%8,%9}, {%0,%1,%2,%3};"
        : "+f"(c[0]), "+f"(c[1]), "+f"(c[2]), "+f"(c[3])
        : "r"(a[0]), "r"(a[1]), "r"(a[2]), "r"(a[3]), "r"(b[0]), "r"(b[1]));
}

// ---------------- zero the atomic accumulators (graph replays!) ----------------
__global__ void zero_ctx_kernel() {
    int i = blockIdx.x * 256 + threadIdx.x;
    if (i < B_ * H_ * C_ * C_) g_ctx[i] = 0.0f;
    if (i < B_ * H_ * C_)      g_sum[i] = 0.0f;
}

// ---------------- round x to fp16 (streaming) ----------------
__global__ void round_f16_kernel(const float4* __restrict__ src, uint2* __restrict__ dst, int n4) {
    int i = blockIdx.x * 256 + threadIdx.x;
    if (i < n4) {
        float4 v = src[i];
        __half2 lo = __floats2half2_rn(v.x, v.y);
        __half2 hi = __floats2half2_rn(v.z, v.w);
        uint2 o;
        o.x = *(uint32_t*)&lo;
        o.y = *(uint32_t*)&hi;
        dst[i] = o;
    }
}

// ---------------- weight transpose + fp16 round: src[R][Ccols] -> dst[Ccols][R] ----------------
__global__ void transpose_f16_kernel(const float* __restrict__ src, __half* __restrict__ dst,
                                     int R, int Ccols) {
    __shared__ float t[32][33];
    int bx = blockIdx.x * 32, by = blockIdx.y * 32;
    int tx = threadIdx.x, ty = threadIdx.y;
#pragma unroll
    for (int j = 0; j < 32; j += 8)
        t[ty + j][tx] = src[(size_t)(by + ty + j) * Ccols + bx + tx];
    __syncthreads();
#pragma unroll
    for (int j = 0; j < 32; j += 8)
        dst[(size_t)(bx + ty + j) * R + by + tx] = __float2half_rn(t[tx][ty + j]);
}

// ================= fp16 m16n8k16 GEMM (block 128x128, BK=32, 8 warps 2x4, warp 64x32) =================
// A [M,K] fp16 row-major, Bt [N,K] fp16 row-major. Out fp32 (+bias).
#define BM_ 128
#define BN_ 128
#define BK_ 32            // halves per chunk
#define PH_ 40            // halves per smem row slot (20 words; conflict-free)

template <int K, int N, int HAS_BIAS>
__global__ void __launch_bounds__(256, 2)
gemm_f16(const __half* __restrict__ A, const __half* __restrict__ Bt,
         const float* __restrict__ bias, float* __restrict__ Cm)
{
    extern __shared__ __half smemh[];
    __half* As = smemh;                       // 2 * 128 * PH_
    __half* Bs = smemh + 2 * BM_ * PH_;       // 2 * 128 * PH_

    const int tid = threadIdx.x;
    const int wid = tid >> 5;
    const int lane = tid & 31;
    const int m0 = blockIdx.y * BM_;
    const int n0 = blockIdx.x * BN_;
    const int wm = (wid & 1) * 64;
    const int wn = (wid >> 1) * 32;
    const int lr = lane >> 2;
    const int lc = lane & 3;
    const int gr = tid >> 2;          // 0..63
    const int gc = (tid & 3) * 8;     // half offset (16B chunks)

    const uint32_t as_base = smem_u32(As);
    const uint32_t bs_base = smem_u32(Bs);

    float acc[4][4][4];
#pragma unroll
    for (int i = 0; i < 4; i++)
#pragma unroll
        for (int j = 0; j < 4; j++)
#pragma unroll
            for (int r = 0; r < 4; r++) acc[i][j][r] = 0.0f;

    constexpr int nch = K / BK_;   // 12

    {
#pragma unroll
        for (int i = 0; i < 2; i++) {
            int row = gr + i * 64;
            cp_async16(as_base + (row * PH_ + gc) * 2, &A[(size_t)(m0 + row) * K + gc]);
            cp_async16(bs_base + (row * PH_ + gc) * 2, &Bt[(size_t)(n0 + row) * K + gc]);
        }
        asm volatile("cp.async.commit_group;");
    }

#pragma unroll
    for (int c = 0; c < nch; c++) {
        asm volatile("cp.async.wait_group 0;");
        __syncthreads();

        if (c + 1 < nch) {
            const int k0 = (c + 1) * BK_;
            const int buf = (c + 1) & 1;
            const uint32_t ab = as_base + buf * BM_ * PH_ * 2;
            const uint32_t bb = bs_base + buf * BN_ * PH_ * 2;
#pragma unroll
            for (int i = 0; i < 2; i++) {
                int row = gr + i * 64;
                cp_async16(ab + (row * PH_ + gc) * 2, &A[(size_t)(m0 + row) * K + k0 + gc]);
                cp_async16(bb + (row * PH_ + gc) * 2, &Bt[(size_t)(n0 + row) * K + k0 + gc]);
            }
            asm volatile("cp.async.commit_group;");
        }

        const uint32_t* asw = (const uint32_t*)(As + (c & 1) * BM_ * PH_);
        const uint32_t* bsw = (const uint32_t*)(Bs + (c & 1) * BN_ * PH_);

#pragma unroll
        for (int ks = 0; ks < 2; ks++) {          // 2 k16-steps per 32-half chunk
            const int kw = ks * 8 + lc;
            uint32_t afr[4][4];
#pragma unroll
            for (int mi = 0; mi < 4; mi++) {
                int r = wm + mi * 16 + lr;
                afr[mi][0] = asw[r * 20 + kw];
                afr[mi][1] = asw[(r + 8) * 20 + kw];
                afr[mi][2] = asw[r * 20 + kw + 4];
                afr[mi][3] = asw[(r + 8) * 20 + kw + 4];
            }
            uint32_t bfr[4][2];
#pragma unroll
            for (int nj = 0; nj < 4; nj++) {
                int nn = wn + nj * 8 + lr;
                bfr[nj][0] = bsw[nn * 20 + kw];
                bfr[nj][1] = bsw[nn * 20 + kw + 4];
            }
#pragma unroll
            for (int mi = 0; mi < 4; mi++)
#pragma unroll
                for (int nj = 0; nj < 4; nj++)
                    mma_f16(acc[mi][nj], afr[mi], bfr[nj]);
        }
        __syncthreads();
    }

#pragma unroll
    for (int mi = 0; mi < 4; mi++) {
        const int r0 = m0 + wm + mi * 16 + lr;
#pragma unroll
        for (int nj = 0; nj < 4; nj++) {
            const int col = n0 + wn + nj * 8 + lc * 2;
            float2 b2 = make_float2(0.f, 0.f);
            if (HAS_BIAS) b2 = *(const float2*)&bias[col];
            float2 v0 = make_float2(acc[mi][nj][0] + b2.x, acc[mi][nj][1] + b2.y);
            float2 v1 = make_float2(acc[mi][nj][2] + b2.x, acc[mi][nj][3] + b2.y);
            *(float2*)&Cm[(size_t)r0 * N + col] = v0;
            *(float2*)&Cm[(size_t)(r0 + 8) * N + col] = v1;
        }
    }
}

// ================= fused kv-GEMM + ctx kernel (fp16) =================
// Grid (4 cg, 256 ss); CTA: 4 rowblocks of 128 tokens; N=192 (k 96 + v 96 chans).
#define KVN_ 192
#define STH_ 136     // eT/vT row stride in halves (68 words; conflict-free)
#define KV_SMEM_BYTES (2 * 96 * STH_ * 2)    // 52224 (>= mainloop 51200)

__global__ void __launch_bounds__(256, 1)
kv_ctx_kernel()
{
    extern __shared__ __half smemh[];
    __half* As = smemh;                          // [2][128][PH_]
    __half* Bs = smemh + 2 * BM_ * PH_;          // [2][192][PH_]
    __half* eT = smemh;                          // [96][STH_]  (epilogue view)
    __half* vT = smemh + 96 * STH_;              // [96][STH_]

    const int tid = threadIdx.x;
    const int wid = tid >> 5;
    const int lane = tid & 31;
    const int cg = blockIdx.x;
    const int ss = blockIdx.y;
    const int lr = lane >> 2;
    const int lc = lane & 3;
    const int wm = (wid & 1) * 64;
    const int wn = (wid >> 1) * 48;
    const int gr = tid >> 2;          // 0..63
    const int gc = (tid & 3) * 8;

    const uint32_t as_base = smem_u32(As);
    const uint32_t bs_base = smem_u32(Bs);

    const __half* Wk = g_Wtqh + (size_t)(D_ + cg * 96) * D_;
    const __half* Wv = g_Wtqh + (size_t)(2 * D_ + cg * 96) * D_;

    const int batch = ss / 32;

    float ctxa[5][4];
#pragma unroll
    for (int i = 0; i < 5; i++)
#pragma unroll
        for (int r = 0; r < 4; r++) ctxa[i][r] = 0.0f;
    float ssum = 0.0f;

    for (int rb = 0; rb < 4; rb++) {
        const size_t tok0 = ((size_t)ss * 4 + rb) * 128;
        const __half* A = g_xh + tok0 * D_;

        float acc[4][6][4];
#pragma unroll
        for (int i = 0; i < 4; i++)
#pragma unroll
            for (int j = 0; j < 6; j++)
#pragma unroll
                for (int r = 0; r < 4; r++) acc[i][j][r] = 0.0f;

        {
#pragma unroll
            for (int i = 0; i < 2; i++) {
                int row = gr + i * 64;
                cp_async16(as_base + (row * PH_ + gc) * 2, &A[(size_t)row * D_ + gc]);
            }
#pragma unroll
            for (int i = 0; i < 3; i++) {
                int row = gr + i * 64;
                const __half* src = (row < 96) ? &Wk[(size_t)row * D_ + gc]
                                               : &Wv[(size_t)(row - 96) * D_ + gc];
                cp_async16(bs_base + (row * PH_ + gc) * 2, src);
            }
            asm volatile("cp.async.commit_group;");
        }

#pragma unroll
        for (int c = 0; c < D_ / BK_; c++) {
            asm volatile("cp.async.wait_group 0;");
            __syncthreads();

            if (c + 1 < D_ / BK_) {
                const int k0 = (c + 1) * BK_;
                const int buf = (c + 1) & 1;
                const uint32_t ab = as_base + buf * BM_ * PH_ * 2;
                const uint32_t bb = bs_base + buf * KVN_ * PH_ * 2;
#pragma unroll
                for (int i = 0; i < 2; i++) {
                    int row = gr + i * 64;
                    cp_async16(ab + (row * PH_ + gc) * 2, &A[(size_t)row * D_ + k0 + gc]);
                }
#pragma unroll
                for (int i = 0; i < 3; i++) {
                    int row = gr + i * 64;
                    const __half* src = (row < 96) ? &Wk[(size_t)row * D_ + k0 + gc]
                                                   : &Wv[(size_t)(row - 96) * D_ + k0 + gc];
                    cp_async16(bb + (row * PH_ + gc) * 2, src);
                }
                asm volatile("cp.async.commit_group;");
            }

            const uint32_t* asw = (const uint32_t*)(As + (c & 1) * BM_ * PH_);
            const uint32_t* bsw = (const uint32_t*)(Bs + (c & 1) * KVN_ * PH_);

#pragma unroll
            for (int ks = 0; ks < 2; ks++) {
                const int kw = ks * 8 + lc;
                uint32_t afr[4][4];
#pragma unroll
                for (int mi = 0; mi < 4; mi++) {
                    int r = wm + mi * 16 + lr;
                    afr[mi][0] = asw[r * 20 + kw];
                    afr[mi][1] = asw[(r + 8) * 20 + kw];
                    afr[mi][2] = asw[r * 20 + kw + 4];
                    afr[mi][3] = asw[(r + 8) * 20 + kw + 4];
                }
                uint32_t bfr[6][2];
#pragma unroll
                for (int nj = 0; nj < 6; nj++) {
                    int nn = wn + nj * 8 + lr;
                    bfr[nj][0] = bsw[nn * 20 + kw];
                    bfr[nj][1] = bsw[nn * 20 + kw + 4];
                }
#pragma unroll
                for (int mi = 0; mi < 4; mi++)
#pragma unroll
                    for (int nj = 0; nj < 6; nj++)
                        mma_f16(acc[mi][nj], afr[mi], bfr[nj]);
            }
            __syncthreads();
        }

        // ---- epilogue: exp(k)^T and v^T into smem as fp16 ----
#pragma unroll
        for (int mi = 0; mi < 4; mi++) {
#pragma unroll
            for (int nj = 0; nj < 6; nj++) {
#pragma unroll
                for (int r = 0; r < 4; r++) {
                    int ch = wn + nj * 8 + lc * 2 + (r & 1);
                    int tl = wm + mi * 16 + lr + ((r >> 1) ? 8 : 0);
                    if (wid < 4) {
                        eT[ch * STH_ + tl] = __float2half_rn(__expf(acc[mi][nj][r]));
                    } else {
                        vT[(ch - 96) * STH_ + tl] = __float2half_rn(acc[mi][nj][r]);
                    }
                }
            }
        }
        __syncthreads();

        // ---- ctx += e^T v via fp16 MMA: 36 m16n8 tiles, k=128 (8 k16-steps) ----
        const uint32_t* eTw = (const uint32_t*)eT;
        const uint32_t* vTw = (const uint32_t*)vT;
#pragma unroll
        for (int i = 0; i < 5; i++) {
            int t = wid + 8 * i;
            if (t < 36) {
                int head = t / 18, rem = t % 18;
                int mi = rem / 6, nj = rem % 6;
                const int ar = head * 48 + mi * 16;
                const int br = head * 48 + nj * 8;
#pragma unroll
                for (int ks = 0; ks < 8; ks++) {
                    const int kw = ks * 8 + lc;
                    uint32_t a[4], b[2];
                    a[0] = eTw[(ar + lr) * 68 + kw];
                    a[1] = eTw[(ar + lr + 8) * 68 + kw];
                    a[2] = eTw[(ar + lr) * 68 + kw + 4];
                    a[3] = eTw[(ar + lr + 8) * 68 + kw + 4];
                    b[0] = vTw[(br + lr) * 68 + kw];
                    b[1] = vTw[(br + lr) * 68 + kw + 4];
                    mma_f16(ctxa[i], a, b);
                }
            }
        }

        // ---- per-channel exp-sum ----
        if (tid < 96) {
            const uint32_t* row = (const uint32_t*)(eT + tid * STH_);
            float s = 0.0f;
#pragma unroll
            for (int j = 0; j < 64; j++) {
                uint32_t w = row[j];
                float2 f = __half22float2(*(const __half2*)&w);
                s += f.x + f.y;
            }
            ssum += s;
        }
        __syncthreads();
    }

    // ---- atomics ----
#pragma unroll
    for (int i = 0; i < 5; i++) {
        int t = wid + 8 * i;
        if (t < 36) {
            int head = t / 18, rem = t % 18;
            int mi = rem / 6, nj = rem % 6;
            int bh = (batch * H_ + cg * 2 + head);
#pragma unroll
            for (int r = 0; r < 4; r++) {
                int c = mi * 16 + lr + ((r >> 1) ? 8 : 0);
                int d = nj * 8 + lc * 2 + (r & 1);
                atomicAdd(&g_ctx[((size_t)bh * C_ + c) * C_ + d], ctxa[i][r]);
            }
        }
    }
    if (tid < 96) {
        int head = tid / 48;
        atomicAdd(&g_sum[(batch * H_ + cg * 2 + head) * C_ + tid % 48], ssum);
    }
}

// ================= global context normalization (one-shot, fp16 out) =================
#define ACT_STH 56
__global__ void ctxn_norm_kernel()
{
    __shared__ float sinv[C_];
    const int bh = blockIdx.x;
    if (threadIdx.x < C_) sinv[threadIdx.x] = 1.0f / g_sum[bh * C_ + threadIdx.x];
    __syncthreads();
    const float* cb = g_ctx + (size_t)bh * (C_ * C_);
    __half* ob = g_ctxnTh + (size_t)bh * (C_ * ACT_STH);
    for (int i = threadIdx.x; i < C_ * C_; i += 256) {
        int c = i / C_, d = i % C_;
        ob[d * ACT_STH + c] = __float2half_rn(cb[i] * sinv[c]);
    }
}

// ================= fp16 HMMA attn: CTA = 128 tokens x 1 head, 128 threads =================
__global__ void __launch_bounds__(128, 4)
attn_tc_kernel()
{
    __shared__ __half eq[128 * ACT_STH];      // 14336 B
    __shared__ __half ctxT[C_ * ACT_STH];     // 5376 B
    __shared__ float srow[128];

    const int tid = threadIdx.x;
    const int wid = tid >> 5;
    const int lane = tid & 31;
    const int lr = lane >> 2;
    const int lc = lane & 3;
    const int h = blockIdx.x & 7;
    const size_t tok0 = (size_t)(blockIdx.x >> 3) * 128;
    const int batch = (int)(tok0 / SEQ_);

    // ---- fill ctxT ----
    {
        const uint2* src = (const uint2*)(g_ctxnTh + ((size_t)batch * H_ + h) * (C_ * ACT_STH));
        uint2* dst = (uint2*)ctxT;
#pragma unroll
        for (int i = tid; i < C_ * ACT_STH / 4; i += 128) dst[i] = src[i];
    }
    // ---- fill eq = fp16(exp(q[:, h*48:+48])) ----
    {
        const float* qb = g_q + tok0 * D_ + h * C_;
        for (int i = tid; i < 128 * 12; i += 128) {
            int r = i / 12, c4 = i % 12;
            float4 v = *(const float4*)&qb[(size_t)r * D_ + c4 * 4];
            __half2 lo = __floats2half2_rn(__expf(v.x), __expf(v.y));
            __half2 hi = __floats2half2_rn(__expf(v.z), __expf(v.w));
            uint2 o; o.x = *(uint32_t*)&lo; o.y = *(uint32_t*)&hi;
            *(uint2*)&eq[r * ACT_STH + c4 * 4] = o;
        }
    }
    __syncthreads();
    // ---- row sums ----
    {
        const uint32_t* rp = (const uint32_t*)(eq + tid * ACT_STH);
        float s = 0.0f;
#pragma unroll
        for (int j = 0; j < 24; j++) {
            uint32_t w = rp[j];
            float2 f = __half22float2(*(const __half2*)&w);
            s += f.x + f.y;
        }
        srow[tid] = 1.0f / s;
    }
    __syncthreads();

    // ---- warp w: rows w*32..+31 ; attn = eq @ ctxT^T (K=48 -> 3 k16-steps) ----
    float acc[2][6][4];
#pragma unroll
    for (int i = 0; i < 2; i++)
#pragma unroll
        for (int j = 0; j < 6; j++)
#pragma unroll
            for (int r = 0; r < 4; r++) acc[i][j][r] = 0.0f;

    const uint32_t* eqw = (const uint32_t*)(eq + wid * 32 * ACT_STH);
    const uint32_t* cw = (const uint32_t*)ctxT;
#pragma unroll
    for (int ks = 0; ks < 3; ks++) {
        const int kw = ks * 8 + lc;
        uint32_t afr[2][4];
#pragma unroll
        for (int mi = 0; mi < 2; mi++) {
            int r = mi * 16 + lr;
            afr[mi][0] = eqw[r * 28 + kw];
            afr[mi][1] = eqw[(r + 8) * 28 + kw];
            afr[mi][2] = eqw[r * 28 + kw + 4];
            afr[mi][3] = eqw[(r + 8) * 28 + kw + 4];
        }
        uint32_t bfr[6][2];
#pragma unroll
        for (int nj = 0; nj < 6; nj++) {
            int nn = nj * 8 + lr;
            bfr[nj][0] = cw[nn * 28 + kw];
            bfr[nj][1] = cw[nn * 28 + kw + 4];
        }
#pragma unroll
        for (int mi = 0; mi < 2; mi++)
#pragma unroll
            for (int nj = 0; nj < 6; nj++)
                mma_f16(acc[mi][nj], afr[mi], bfr[nj]);
    }

    // ---- scale + write fp16 ----
    __half* ob = g_attnh + tok0 * D_ + h * C_;
#pragma unroll
    for (int mi = 0; mi < 2; mi++) {
        const int ra = wid * 32 + mi * 16 + lr;
        const float sa = srow[ra];
        const float sb = srow[ra + 8];
#pragma unroll
        for (int nj = 0; nj < 6; nj++) {
            const int col = nj * 8 + lc * 2;
            __half2 v0 = __floats2half2_rn(acc[mi][nj][0] * sa, acc[mi][nj][1] * sa);
            __half2 v1 = __floats2half2_rn(acc[mi][nj][2] * sb, acc[mi][nj][3] * sb);
            *(__half2*)&ob[(size_t)ra * D_ + col] = v0;
            *(__half2*)&ob[(size_t)(ra + 8) * D_ + col] = v1;
        }
    }
}

// ---------------- launch ----------------
extern "C" void kernel_launch(void* const* d_in, const int* in_sizes, int n_in,
                              void* d_out, int out_size)
{
    const float* x     = (const float*)d_in[0];
    const float* Wqkv  = (const float*)d_in[1];
    const float* Wproj = (const float*)d_in[2];
    const float* bproj = (const float*)d_in[3];
    float* out = (float*)d_out;

    float* p_q;
    __half *p_xh, *p_attnh, *p_wtqh, *p_wtph;
    cudaGetSymbolAddress((void**)&p_q, g_q);
    cudaGetSymbolAddress((void**)&p_xh, g_xh);
    cudaGetSymbolAddress((void**)&p_attnh, g_attnh);
    cudaGetSymbolAddress((void**)&p_wtqh, g_Wtqh);
    cudaGetSymbolAddress((void**)&p_wtph, g_Wtph);

    const int gemm_smem = 4 * BM_ * PH_ * 2;     // 40960
    cudaFuncSetAttribute(gemm_f16<D_, D_, 0>, cudaFuncAttributeMaxDynamicSharedMemorySize, gemm_smem);
    cudaFuncSetAttribute(gemm_f16<D_, D_, 1>, cudaFuncAttributeMaxDynamicSharedMemorySize, gemm_smem);
    cudaFuncSetAttribute(kv_ctx_kernel, cudaFuncAttributeMaxDynamicSharedMemorySize, KV_SMEM_BYTES);

    // 0) prepasses
    {
        int n4 = TOK_ * D_ / 4;
        round_f16_kernel<<<(n4 + 255) / 256, 256>>>((const float4*)x, (uint2*)p_xh, n4);
    }
    transpose_f16_kernel<<<dim3(3 * D_ / 32, D_ / 32), dim3(32, 8)>>>(Wqkv, p_wtqh, D_, 3 * D_);
    transpose_f16_kernel<<<dim3(D_ / 32, D_ / 32), dim3(32, 8)>>>(Wproj, p_wtph, D_, D_);
    zero_ctx_kernel<<<(B_ * H_ * C_ * C_ + 255) / 256, 256>>>();

    // 1) q = x @ Wq  (fp32 out)
    {
        dim3 grid(D_ / BN_, TOK_ / BM_);
        gemm_f16<D_, D_, 0><<<grid, 256, gemm_smem>>>(p_xh, p_wtqh, nullptr, p_q);
    }

    // 2) fused kv-GEMM + context accumulation
    {
        dim3 grid(4, 256);
        kv_ctx_kernel<<<grid, 256, KV_SMEM_BYTES>>>();
    }

    // 3) one-shot context normalization
    ctxn_norm_kernel<<<B_ * H_, 256>>>();

    // 4) fp16 HMMA attn (writes g_attnh)
    attn_tc_kernel<<<(TOK_ / 128) * H_, 128>>>();

    // 5) out = attn @ W_proj + b_proj
    {
        dim3 grid(D_ / BN_, TOK_ / BM_);
        gemm_f16<D_, D_, 1><<<grid, 256, gemm_smem>>>(p_attnh, p_wtph, bproj, out);
    }
}

// round 11
// speedup vs baseline: 1.9291x; 1.1301x over previous
#include <cuda_runtime.h>
#include <cuda_fp16.h>
#include <math.h>
#include <stdint.h>

// Problem constants
#define B_      8
#define SEQ_    16384
#define D_      384
#define H_      8
#define C_      48
#define TOK_    (B_ * SEQ_)          // 131072

// ---------------- scratch (static device globals; no allocs allowed) ----------------
__device__ __half g_eqh[(size_t)TOK_ * D_];          // 100 MB : exp(q) fp16
__device__ __half g_attnh[(size_t)TOK_ * D_];        // 100 MB : attention output (fp16)
__device__ __half g_xh[(size_t)TOK_ * D_];           // 100 MB : x rounded to fp16
__device__ float  g_ctx[B_ * H_ * C_ * C_];          // unnormalized k^T v context
__device__ float  g_sum[B_ * H_ * C_];               // sum of exp(k) over tokens
__device__ __half g_ctxnTh[B_ * H_ * C_ * 56];       // normalized, transposed, fp16, padded
__device__ __half g_Wtqh[3 * D_ * D_];               // W_qkv^T, fp16  [1152][384]
__device__ __half g_Wtph[D_ * D_];                   // W_proj^T, fp16

__device__ __forceinline__ uint32_t smem_u32(const void* p) {
    uint32_t a;
    asm("{ .reg .u64 t; cvta.to.shared.u64 t, %1; cvt.u32.u64 %0, t; }" : "=r"(a) : "l"(p));
    return a;
}
__device__ __forceinline__ void cp_async16(uint32_t dst, const void* src) {
    asm volatile("cp.async.cg.shared.global [%0], [%1], 16;" :: "r"(dst), "l"(src));
}
__device__ __forceinline__ void mma_f16(float* c, const uint32_t* a, const uint32_t* b) {
    asm volatile(
        "mma.sync.aligned.m16n8k16.row.col.f32.f16.f16.f32 "
        "{%0,%1,%2,%3}, {%4,%5,%6,%7}, {%8,%9}, {%0,%1,%2,%3};"
        : "+f"(c[0]), "+f"(c[1]), "+f"(c[2]), "+f"(c[3])
        : "r"(a[0]), "r"(a[1]), "r"(a[2]), "r"(a[3]), "r"(b[0]), "r"(b[1]));
}

// ---------------- zero the atomic accumulators (graph replays!) ----------------
__global__ void zero_ctx_kernel() {
    int i = blockIdx.x * 256 + threadIdx.x;
    if (i < B_ * H_ * C_ * C_) g_ctx[i] = 0.0f;
    if (i < B_ * H_ * C_)      g_sum[i] = 0.0f;
}

// ---------------- round x to fp16 (streaming) ----------------
__global__ void round_f16_kernel(const float4* __restrict__ src, uint2* __restrict__ dst, int n4) {
    int i = blockIdx.x * 256 + threadIdx.x;
    if (i < n4) {
        float4 v = src[i];
        __half2 lo = __floats2half2_rn(v.x, v.y);
        __half2 hi = __floats2half2_rn(v.z, v.w);
        uint2 o;
        o.x = *(uint32_t*)&lo;
        o.y = *(uint32_t*)&hi;
        dst[i] = o;
    }
}

// ---------------- weight transpose + fp16 round: src[R][Ccols] -> dst[Ccols][R] ----------------
__global__ void transpose_f16_kernel(const float* __restrict__ src, __half* __restrict__ dst,
                                     int R, int Ccols) {
    __shared__ float t[32][33];
    int bx = blockIdx.x * 32, by = blockIdx.y * 32;
    int tx = threadIdx.x, ty = threadIdx.y;
#pragma unroll
    for (int j = 0; j < 32; j += 8)
        t[ty + j][tx] = src[(size_t)(by + ty + j) * Ccols + bx + tx];
    __syncthreads();
#pragma unroll
    for (int j = 0; j < 32; j += 8)
        dst[(size_t)(bx + ty + j) * R + by + tx] = __float2half_rn(t[tx][ty + j]);
}

// ================= fp16 m16n8k16 GEMM (proj) =================
#define BM_ 128
#define BN_ 128
#define BK_ 32            // halves per chunk
#define PH_ 40            // halves per smem row slot (20 words; conflict-free)

template <int K, int N, int HAS_BIAS>
__global__ void __launch_bounds__(256, 2)
gemm_f16(const __half* __restrict__ A, const __half* __restrict__ Bt,
         const float* __restrict__ bias, float* __restrict__ Cm)
{
    extern __shared__ __half smemh[];
    __half* As = smemh;
    __half* Bs = smemh + 2 * BM_ * PH_;

    const int tid = threadIdx.x;
    const int wid = tid >> 5;
    const int lane = tid & 31;
    const int m0 = blockIdx.y * BM_;
    const int n0 = blockIdx.x * BN_;
    const int wm = (wid & 1) * 64;
    const int wn = (wid >> 1) * 32;
    const int lr = lane >> 2;
    const int lc = lane & 3;
    const int gr = tid >> 2;
    const int gc = (tid & 3) * 8;

    const uint32_t as_base = smem_u32(As);
    const uint32_t bs_base = smem_u32(Bs);

    float acc[4][4][4];
#pragma unroll
    for (int i = 0; i < 4; i++)
#pragma unroll
        for (int j = 0; j < 4; j++)
#pragma unroll
            for (int r = 0; r < 4; r++) acc[i][j][r] = 0.0f;

    constexpr int nch = K / BK_;

    {
#pragma unroll
        for (int i = 0; i < 2; i++) {
            int row = gr + i * 64;
            cp_async16(as_base + (row * PH_ + gc) * 2, &A[(size_t)(m0 + row) * K + gc]);
            cp_async16(bs_base + (row * PH_ + gc) * 2, &Bt[(size_t)(n0 + row) * K + gc]);
        }
        asm volatile("cp.async.commit_group;");
    }

#pragma unroll
    for (int c = 0; c < nch; c++) {
        asm volatile("cp.async.wait_group 0;");
        __syncthreads();

        if (c + 1 < nch) {
            const int k0 = (c + 1) * BK_;
            const int buf = (c + 1) & 1;
            const uint32_t ab = as_base + buf * BM_ * PH_ * 2;
            const uint32_t bb = bs_base + buf * BN_ * PH_ * 2;
#pragma unroll
            for (int i = 0; i < 2; i++) {
                int row = gr + i * 64;
                cp_async16(ab + (row * PH_ + gc) * 2, &A[(size_t)(m0 + row) * K + k0 + gc]);
                cp_async16(bb + (row * PH_ + gc) * 2, &Bt[(size_t)(n0 + row) * K + k0 + gc]);
            }
            asm volatile("cp.async.commit_group;");
        }

        const uint32_t* asw = (const uint32_t*)(As + (c & 1) * BM_ * PH_);
        const uint32_t* bsw = (const uint32_t*)(Bs + (c & 1) * BN_ * PH_);

#pragma unroll
        for (int ks = 0; ks < 2; ks++) {
            const int kw = ks * 8 + lc;
            uint32_t afr[4][4];
#pragma unroll
            for (int mi = 0; mi < 4; mi++) {
                int r = wm + mi * 16 + lr;
                afr[mi][0] = asw[r * 20 + kw];
                afr[mi][1] = asw[(r + 8) * 20 + kw];
                afr[mi][2] = asw[r * 20 + kw + 4];
                afr[mi][3] = asw[(r + 8) * 20 + kw + 4];
            }
            uint32_t bfr[4][2];
#pragma unroll
            for (int nj = 0; nj < 4; nj++) {
                int nn = wn + nj * 8 + lr;
                bfr[nj][0] = bsw[nn * 20 + kw];
                bfr[nj][1] = bsw[nn * 20 + kw + 4];
            }
#pragma unroll
            for (int mi = 0; mi < 4; mi++)
#pragma unroll
                for (int nj = 0; nj < 4; nj++)
                    mma_f16(acc[mi][nj], afr[mi], bfr[nj]);
        }
        __syncthreads();
    }

#pragma unroll
    for (int mi = 0; mi < 4; mi++) {
        const int r0 = m0 + wm + mi * 16 + lr;
#pragma unroll
        for (int nj = 0; nj < 4; nj++) {
            const int col = n0 + wn + nj * 8 + lc * 2;
            float2 b2 = make_float2(0.f, 0.f);
            if (HAS_BIAS) b2 = *(const float2*)&bias[col];
            float2 v0 = make_float2(acc[mi][nj][0] + b2.x, acc[mi][nj][1] + b2.y);
            float2 v1 = make_float2(acc[mi][nj][2] + b2.x, acc[mi][nj][3] + b2.y);
            *(float2*)&Cm[(size_t)r0 * N + col] = v0;
            *(float2*)&Cm[(size_t)(r0 + 8) * N + col] = v1;
        }
    }
}

// ================= fused qkv-GEMM + ctx kernel =================
// Grid (4 cg, 256 ss). Per cg: N=288 = 96 q + 96 k + 96 v channels (heads 2cg,2cg+1).
// q -> exp -> fp16 gmem (g_eqh). k -> exp -> eT smem; v -> vT smem; ctx += e^T v (MMA).
#define KVN_ 288
#define STH_ 136     // eT/vT row stride in halves (68 words)
#define KV_SMEM_BYTES ((2 * BM_ * PH_ + 2 * KVN_ * PH_) * 2)   // 66560 (>= eT/vT view 52224)

__global__ void __launch_bounds__(256, 1)
kv_ctx_kernel()
{
    extern __shared__ __half smemh[];
    __half* As = smemh;                          // [2][128][PH_]
    __half* Bs = smemh + 2 * BM_ * PH_;          // [2][288][PH_]
    __half* eT = smemh;                          // [96][STH_]  (epilogue view)
    __half* vT = smemh + 96 * STH_;              // [96][STH_]

    const int tid = threadIdx.x;
    const int wid = tid >> 5;
    const int lane = tid & 31;
    const int cg = blockIdx.x;
    const int ss = blockIdx.y;
    const int lr = lane >> 2;
    const int lc = lane & 3;
    const int wm = (wid & 1) * 64;
    const int wn = (wid >> 1) * 72;   // 4 warps over N=288
    const int gr = tid >> 2;          // 0..63
    const int gc = (tid & 3) * 8;

    const uint32_t as_base = smem_u32(As);
    const uint32_t bs_base = smem_u32(Bs);

    const __half* Wq = g_Wtqh + (size_t)(cg * 96) * D_;
    const __half* Wk = g_Wtqh + (size_t)(D_ + cg * 96) * D_;
    const __half* Wv = g_Wtqh + (size_t)(2 * D_ + cg * 96) * D_;

    const int batch = ss / 32;

    float ctxa[5][4];
#pragma unroll
    for (int i = 0; i < 5; i++)
#pragma unroll
        for (int r = 0; r < 4; r++) ctxa[i][r] = 0.0f;
    float ssum = 0.0f;

    for (int rb = 0; rb < 4; rb++) {
        const size_t tok0 = ((size_t)ss * 4 + rb) * 128;
        const __half* A = g_xh + tok0 * D_;

        float acc[4][9][4];
#pragma unroll
        for (int i = 0; i < 4; i++)
#pragma unroll
            for (int j = 0; j < 9; j++)
#pragma unroll
                for (int r = 0; r < 4; r++) acc[i][j][r] = 0.0f;

        {
#pragma unroll
            for (int i = 0; i < 2; i++) {
                int row = gr + i * 64;
                cp_async16(as_base + (row * PH_ + gc) * 2, &A[(size_t)row * D_ + gc]);
            }
#pragma unroll
            for (int i = 0; i < 5; i++) {
                int row = gr + i * 64;
                if (row < KVN_) {
                    const __half* src = (row < 96) ? &Wq[(size_t)row * D_ + gc]
                                     : (row < 192) ? &Wk[(size_t)(row - 96) * D_ + gc]
                                                   : &Wv[(size_t)(row - 192) * D_ + gc];
                    cp_async16(bs_base + (row * PH_ + gc) * 2, src);
                }
            }
            asm volatile("cp.async.commit_group;");
        }

#pragma unroll
        for (int c = 0; c < D_ / BK_; c++) {
            asm volatile("cp.async.wait_group 0;");
            __syncthreads();

            if (c + 1 < D_ / BK_) {
                const int k0 = (c + 1) * BK_;
                const int buf = (c + 1) & 1;
                const uint32_t ab = as_base + buf * BM_ * PH_ * 2;
                const uint32_t bb = bs_base + buf * KVN_ * PH_ * 2;
#pragma unroll
                for (int i = 0; i < 2; i++) {
                    int row = gr + i * 64;
                    cp_async16(ab + (row * PH_ + gc) * 2, &A[(size_t)row * D_ + k0 + gc]);
                }
#pragma unroll
                for (int i = 0; i < 5; i++) {
                    int row = gr + i * 64;
                    if (row < KVN_) {
                        const __half* src = (row < 96) ? &Wq[(size_t)row * D_ + k0 + gc]
                                         : (row < 192) ? &Wk[(size_t)(row - 96) * D_ + k0 + gc]
                                                       : &Wv[(size_t)(row - 192) * D_ + k0 + gc];
                        cp_async16(bb + (row * PH_ + gc) * 2, src);
                    }
                }
                asm volatile("cp.async.commit_group;");
            }

            const uint32_t* asw = (const uint32_t*)(As + (c & 1) * BM_ * PH_);
            const uint32_t* bsw = (const uint32_t*)(Bs + (c & 1) * KVN_ * PH_);

#pragma unroll
            for (int ks = 0; ks < 2; ks++) {
                const int kw = ks * 8 + lc;
                uint32_t afr[4][4];
#pragma unroll
                for (int mi = 0; mi < 4; mi++) {
                    int r = wm + mi * 16 + lr;
                    afr[mi][0] = asw[r * 20 + kw];
                    afr[mi][1] = asw[(r + 8) * 20 + kw];
                    afr[mi][2] = asw[r * 20 + kw + 4];
                    afr[mi][3] = asw[(r + 8) * 20 + kw + 4];
                }
                uint32_t bfr[9][2];
#pragma unroll
                for (int nj = 0; nj < 9; nj++) {
                    int nn = wn + nj * 8 + lr;
                    bfr[nj][0] = bsw[nn * 20 + kw];
                    bfr[nj][1] = bsw[nn * 20 + kw + 4];
                }
#pragma unroll
                for (int mi = 0; mi < 4; mi++)
#pragma unroll
                    for (int nj = 0; nj < 9; nj++)
                        mma_f16(acc[mi][nj], afr[mi], bfr[nj]);
            }
            __syncthreads();
        }

        // ---- epilogue: q -> exp -> gmem fp16 ; k -> exp -> eT ; v -> vT ----
        {
            __half* eqb = g_eqh + tok0 * D_ + cg * 96;
#pragma unroll
            for (int nj = 0; nj < 9; nj++) {
                const int chbase = wn + nj * 8;
                if (chbase < 96) {
                    // q: token-major half2 stores to gmem
                    const int ch = chbase + lc * 2;
#pragma unroll
                    for (int mi = 0; mi < 4; mi++) {
                        int tl = wm + mi * 16 + lr;
                        __half2 v0 = __floats2half2_rn(__expf(acc[mi][nj][0]), __expf(acc[mi][nj][1]));
                        __half2 v1 = __floats2half2_rn(__expf(acc[mi][nj][2]), __expf(acc[mi][nj][3]));
                        *(__half2*)&eqb[(size_t)tl * D_ + ch] = v0;
                        *(__half2*)&eqb[(size_t)(tl + 8) * D_ + ch] = v1;
                    }
                } else if (chbase < 192) {
#pragma unroll
                    for (int mi = 0; mi < 4; mi++) {
#pragma unroll
                        for (int r = 0; r < 4; r++) {
                            int ch = chbase - 96 + lc * 2 + (r & 1);
                            int tl = wm + mi * 16 + lr + ((r >> 1) ? 8 : 0);
                            eT[ch * STH_ + tl] = __float2half_rn(__expf(acc[mi][nj][r]));
                        }
                    }
                } else {
#pragma unroll
                    for (int mi = 0; mi < 4; mi++) {
#pragma unroll
                        for (int r = 0; r < 4; r++) {
                            int ch = chbase - 192 + lc * 2 + (r & 1);
                            int tl = wm + mi * 16 + lr + ((r >> 1) ? 8 : 0);
                            vT[ch * STH_ + tl] = __float2half_rn(acc[mi][nj][r]);
                        }
                    }
                }
            }
        }
        __syncthreads();

        // ---- ctx += e^T v via fp16 MMA: 36 m16n8 tiles, k=128 (8 k16-steps) ----
        const uint32_t* eTw = (const uint32_t*)eT;
        const uint32_t* vTw = (const uint32_t*)vT;
#pragma unroll
        for (int i = 0; i < 5; i++) {
            int t = wid + 8 * i;
            if (t < 36) {
                int head = t / 18, rem = t % 18;
                int mi = rem / 6, nj = rem % 6;
                const int ar = head * 48 + mi * 16;
                const int br = head * 48 + nj * 8;
#pragma unroll
                for (int ks = 0; ks < 8; ks++) {
                    const int kw = ks * 8 + lc;
                    uint32_t a[4], b[2];
                    a[0] = eTw[(ar + lr) * 68 + kw];
                    a[1] = eTw[(ar + lr + 8) * 68 + kw];
                    a[2] = eTw[(ar + lr) * 68 + kw + 4];
                    a[3] = eTw[(ar + lr + 8) * 68 + kw + 4];
                    b[0] = vTw[(br + lr) * 68 + kw];
                    b[1] = vTw[(br + lr) * 68 + kw + 4];
                    mma_f16(ctxa[i], a, b);
                }
            }
        }

        // ---- per-channel exp-sum ----
        if (tid < 96) {
            const uint32_t* row = (const uint32_t*)(eT + tid * STH_);
            float s = 0.0f;
#pragma unroll
            for (int j = 0; j < 64; j++) {
                uint32_t w = row[j];
                float2 f = __half22float2(*(const __half2*)&w);
                s += f.x + f.y;
            }
            ssum += s;
        }
        __syncthreads();
    }

    // ---- atomics ----
#pragma unroll
    for (int i = 0; i < 5; i++) {
        int t = wid + 8 * i;
        if (t < 36) {
            int head = t / 18, rem = t % 18;
            int mi = rem / 6, nj = rem % 6;
            int bh = (batch * H_ + cg * 2 + head);
#pragma unroll
            for (int r = 0; r < 4; r++) {
                int c = mi * 16 + lr + ((r >> 1) ? 8 : 0);
                int d = nj * 8 + lc * 2 + (r & 1);
                atomicAdd(&g_ctx[((size_t)bh * C_ + c) * C_ + d], ctxa[i][r]);
            }
        }
    }
    if (tid < 96) {
        int head = tid / 48;
        atomicAdd(&g_sum[(batch * H_ + cg * 2 + head) * C_ + tid % 48], ssum);
    }
}

// ================= global context normalization (one-shot, fp16 out) =================
#define ACT_STH 56
__global__ void ctxn_norm_kernel()
{
    __shared__ float sinv[C_];
    const int bh = blockIdx.x;
    if (threadIdx.x < C_) sinv[threadIdx.x] = 1.0f / g_sum[bh * C_ + threadIdx.x];
    __syncthreads();
    const float* cb = g_ctx + (size_t)bh * (C_ * C_);
    __half* ob = g_ctxnTh + (size_t)bh * (C_ * ACT_STH);
    for (int i = threadIdx.x; i < C_ * C_; i += 256) {
        int c = i / C_, d = i % C_;
        ob[d * ACT_STH + c] = __float2half_rn(cb[i] * sinv[c]);
    }
}

// ================= fp16 HMMA attn: CTA = 128 tokens x 1 head, 128 threads =================
__global__ void __launch_bounds__(128, 4)
attn_tc_kernel()
{
    __shared__ __half eq[128 * ACT_STH];      // 14336 B
    __shared__ __half ctxT[C_ * ACT_STH];     // 5376 B
    __shared__ float srow[128];

    const int tid = threadIdx.x;
    const int wid = tid >> 5;
    const int lane = tid & 31;
    const int lr = lane >> 2;
    const int lc = lane & 3;
    const int h = blockIdx.x & 7;
    const size_t tok0 = (size_t)(blockIdx.x >> 3) * 128;
    const int batch = (int)(tok0 / SEQ_);

    // ---- fill ctxT ----
    {
        const uint2* src = (const uint2*)(g_ctxnTh + ((size_t)batch * H_ + h) * (C_ * ACT_STH));
        uint2* dst = (uint2*)ctxT;
#pragma unroll
        for (int i = tid; i < C_ * ACT_STH / 4; i += 128) dst[i] = src[i];
    }
    // ---- fill eq from precomputed exp(q) fp16 ----
    {
        const __half* qb = g_eqh + tok0 * D_ + h * C_;
        for (int i = tid; i < 128 * 12; i += 128) {
            int r = i / 12, c4 = i % 12;
            uint2 v = *(const uint2*)&qb[(size_t)r * D_ + c4 * 4];
            *(uint2*)&eq[r * ACT_STH + c4 * 4] = v;
        }
    }
    __syncthreads();
    // ---- row sums ----
    {
        const uint32_t* rp = (const uint32_t*)(eq + tid * ACT_STH);
        float s = 0.0f;
#pragma unroll
        for (int j = 0; j < 24; j++) {
            uint32_t w = rp[j];
            float2 f = __half22float2(*(const __half2*)&w);
            s += f.x + f.y;
        }
        srow[tid] = 1.0f / s;
    }
    __syncthreads();

    // ---- warp w: rows w*32..+31 ; attn = eq @ ctxT^T (K=48 -> 3 k16-steps) ----
    float acc[2][6][4];
#pragma unroll
    for (int i = 0; i < 2; i++)
#pragma unroll
        for (int j = 0; j < 6; j++)
#pragma unroll
            for (int r = 0; r < 4; r++) acc[i][j][r] = 0.0f;

    const uint32_t* eqw = (const uint32_t*)(eq + wid * 32 * ACT_STH);
    const uint32_t* cw = (const uint32_t*)ctxT;
#pragma unroll
    for (int ks = 0; ks < 3; ks++) {
        const int kw = ks * 8 + lc;
        uint32_t afr[2][4];
#pragma unroll
        for (int mi = 0; mi < 2; mi++) {
            int r = mi * 16 + lr;
            afr[mi][0] = eqw[r * 28 + kw];
            afr[mi][1] = eqw[(r + 8) * 28 + kw];
            afr[mi][2] = eqw[r * 28 + kw + 4];
            afr[mi][3] = eqw[(r + 8) * 28 + kw + 4];
        }
        uint32_t bfr[6][2];
#pragma unroll
        for (int nj = 0; nj < 6; nj++) {
            int nn = nj * 8 + lr;
            bfr[nj][0] = cw[nn * 28 + kw];
            bfr[nj][1] = cw[nn * 28 + kw + 4];
        }
#pragma unroll
        for (int mi = 0; mi < 2; mi++)
#pragma unroll
            for (int nj = 0; nj < 6; nj++)
                mma_f16(acc[mi][nj], afr[mi], bfr[nj]);
    }

    // ---- scale + write fp16 ----
    __half* ob = g_attnh + tok0 * D_ + h * C_;
#pragma unroll
    for (int mi = 0; mi < 2; mi++) {
        const int ra = wid * 32 + mi * 16 + lr;
        const float sa = srow[ra];
        const float sb = srow[ra + 8];
#pragma unroll
        for (int nj = 0; nj < 6; nj++) {
            const int col = nj * 8 + lc * 2;
            __half2 v0 = __floats2half2_rn(acc[mi][nj][0] * sa, acc[mi][nj][1] * sa);
            __half2 v1 = __floats2half2_rn(acc[mi][nj][2] * sb, acc[mi][nj][3] * sb);
            *(__half2*)&ob[(size_t)ra * D_ + col] = v0;
            *(__half2*)&ob[(size_t)(ra + 8) * D_ + col] = v1;
        }
    }
}

// ---------------- launch ----------------
extern "C" void kernel_launch(void* const* d_in, const int* in_sizes, int n_in,
                              void* d_out, int out_size)
{
    const float* x     = (const float*)d_in[0];
    const float* Wqkv  = (const float*)d_in[1];
    const float* Wproj = (const float*)d_in[2];
    const float* bproj = (const float*)d_in[3];
    float* out = (float*)d_out;

    __half *p_xh, *p_attnh, *p_wtqh, *p_wtph;
    cudaGetSymbolAddress((void**)&p_xh, g_xh);
    cudaGetSymbolAddress((void**)&p_attnh, g_attnh);
    cudaGetSymbolAddress((void**)&p_wtqh, g_Wtqh);
    cudaGetSymbolAddress((void**)&p_wtph, g_Wtph);

    const int gemm_smem = 4 * BM_ * PH_ * 2;     // 40960
    cudaFuncSetAttribute(gemm_f16<D_, D_, 1>, cudaFuncAttributeMaxDynamicSharedMemorySize, gemm_smem);
    cudaFuncSetAttribute(kv_ctx_kernel, cudaFuncAttributeMaxDynamicSharedMemorySize, KV_SMEM_BYTES);

    // 0) prepasses
    zero_ctx_kernel<<<(B_ * H_ * C_ * C_ + 255) / 256, 256>>>();
    {
        int n4 = TOK_ * D_ / 4;
        round_f16_kernel<<<(n4 + 255) / 256, 256>>>((const float4*)x, (uint2*)p_xh, n4);
    }
    transpose_f16_kernel<<<dim3(3 * D_ / 32, D_ / 32), dim3(32, 8)>>>(Wqkv, p_wtqh, D_, 3 * D_);
    transpose_f16_kernel<<<dim3(D_ / 32, D_ / 32), dim3(32, 8)>>>(Wproj, p_wtph, D_, D_);

    // 1) fused qkv-GEMM + exp + context accumulation (writes g_eqh, g_ctx, g_sum)
    {
        dim3 grid(4, 256);
        kv_ctx_kernel<<<grid, 256, KV_SMEM_BYTES>>>();
    }

    // 2) one-shot context normalization
    ctxn_norm_kernel<<<B_ * H_, 256>>>();

    // 3) fp16 HMMA attn (reads g_eqh, writes g_attnh)
    attn_tc_kernel<<<(TOK_ / 128) * H_, 128>>>();

    // 4) out = attn @ W_proj + b_proj
    {
        dim3 grid(D_ / BN_, TOK_ / BM_);
        gemm_f16<D_, D_, 1><<<grid, 256, gemm_smem>>>(p_attnh, p_wtph, bproj, out);
    }
}

// round 12
// speedup vs baseline: 1.9924x; 1.0328x over previous
#include <cuda_runtime.h>
#include <cuda_fp16.h>
#include <math.h>
#include <stdint.h>

// Problem constants
#define B_      8
#define SEQ_    16384
#define D_      384
#define H_      8
#define C_      48
#define TOK_    (B_ * SEQ_)          // 131072

// ---------------- scratch (static device globals; no allocs allowed) ----------------
__device__ __half g_eqh[(size_t)TOK_ * D_];          // 100 MB : exp(q) fp16
__device__ __half g_attnh[(size_t)TOK_ * D_];        // 100 MB : attention output (fp16)
__device__ __half g_xh[(size_t)TOK_ * D_];           // 100 MB : x rounded to fp16
__device__ float  g_ctx[B_ * H_ * C_ * C_];          // unnormalized k^T v context
__device__ float  g_sum[B_ * H_ * C_];               // sum of exp(k) over tokens
__device__ __half g_ctxnTh[B_ * H_ * C_ * 56];       // normalized, transposed, fp16, padded
__device__ __half g_Wtqh[3 * D_ * D_];               // W_qkv^T, fp16  [1152][384]
__device__ __half g_Wtph[D_ * D_];                   // W_proj^T, fp16

__device__ __forceinline__ uint32_t smem_u32(const void* p) {
    uint32_t a;
    asm("{ .reg .u64 t; cvta.to.shared.u64 t, %1; cvt.u32.u64 %0, t; }" : "=r"(a) : "l"(p));
    return a;
}
__device__ __forceinline__ void cp_async16(uint32_t dst, const void* src) {
    asm volatile("cp.async.cg.shared.global [%0], [%1], 16;" :: "r"(dst), "l"(src));
}
__device__ __forceinline__ void mma_f16(float* c, const uint32_t* a, const uint32_t* b) {
    asm volatile(
        "mma.sync.aligned.m16n8k16.row.col.f32.f16.f16.f32 "
        "{%0,%1,%2,%3}, {%4,%5,%6,%7}, {%8,%9}, {%0,%1,%2,%3};"
        : "+f"(c[0]), "+f"(c[1]), "+f"(c[2]), "+f"(c[3])
        : "r"(a[0]), "r"(a[1]), "r"(a[2]), "r"(a[3]), "r"(b[0]), "r"(b[1]));
}
#define LDMX4(r0, r1, r2, r3, addr) \
    asm volatile("ldmatrix.sync.aligned.m8n8.x4.shared.b16 {%0,%1,%2,%3}, [%4];" \
        : "=r"(r0), "=r"(r1), "=r"(r2), "=r"(r3) : "r"(addr))
#define LDMX2(r0, r1, addr) \
    asm volatile("ldmatrix.sync.aligned.m8n8.x2.shared.b16 {%0,%1}, [%2];" \
        : "=r"(r0), "=r"(r1) : "r"(addr))

// ---------------- zero the atomic accumulators (graph replays!) ----------------
__global__ void zero_ctx_kernel() {
    int i = blockIdx.x * 256 + threadIdx.x;
    if (i < B_ * H_ * C_ * C_) g_ctx[i] = 0.0f;
    if (i < B_ * H_ * C_)      g_sum[i] = 0.0f;
}

// ---------------- round x to fp16 (streaming) ----------------
__global__ void round_f16_kernel(const float4* __restrict__ src, uint2* __restrict__ dst, int n4) {
    int i = blockIdx.x * 256 + threadIdx.x;
    if (i < n4) {
        float4 v = src[i];
        __half2 lo = __floats2half2_rn(v.x, v.y);
        __half2 hi = __floats2half2_rn(v.z, v.w);
        uint2 o;
        o.x = *(uint32_t*)&lo;
        o.y = *(uint32_t*)&hi;
        dst[i] = o;
    }
}

// ---------------- weight transpose + fp16 round: src[R][Ccols] -> dst[Ccols][R] ----------------
__global__ void transpose_f16_kernel(const float* __restrict__ src, __half* __restrict__ dst,
                                     int R, int Ccols) {
    __shared__ float t[32][33];
    int bx = blockIdx.x * 32, by = blockIdx.y * 32;
    int tx = threadIdx.x, ty = threadIdx.y;
#pragma unroll
    for (int j = 0; j < 32; j += 8)
        t[ty + j][tx] = src[(size_t)(by + ty + j) * Ccols + bx + tx];
    __syncthreads();
#pragma unroll
    for (int j = 0; j < 32; j += 8)
        dst[(size_t)(bx + ty + j) * R + by + tx] = __float2half_rn(t[tx][ty + j]);
}

// ================= fp16 m16n8k16 GEMM (proj) — ldmatrix fragments =================
#define BM_ 128
#define BN_ 128
#define BK_ 32            // halves per chunk
#define PH_ 40            // halves per smem row slot (80B; ldmatrix conflict-free)

template <int K, int N, int HAS_BIAS>
__global__ void __launch_bounds__(256, 2)
gemm_f16(const __half* __restrict__ A, const __half* __restrict__ Bt,
         const float* __restrict__ bias, float* __restrict__ Cm)
{
    extern __shared__ __half smemh[];
    __half* As = smemh;
    __half* Bs = smemh + 2 * BM_ * PH_;

    const int tid = threadIdx.x;
    const int wid = tid >> 5;
    const int lane = tid & 31;
    const int m0 = blockIdx.y * BM_;
    const int n0 = blockIdx.x * BN_;
    const int wm = (wid & 1) * 64;
    const int wn = (wid >> 1) * 32;
    const int lr = lane >> 2;
    const int lc = lane & 3;
    const int gr = tid >> 2;
    const int gc = (tid & 3) * 8;

    const uint32_t as_base = smem_u32(As);
    const uint32_t bs_base = smem_u32(Bs);

    // ldmatrix lane-address offsets (bytes, relative to buffer start)
    const int lrow = lane & 7;
    const uint32_t a_lane = ((wm + lrow + ((lane >> 3) & 1) * 8) * PH_ + ((lane >> 4) & 1) * 8) * 2;
    const uint32_t b_lane = ((wn + lrow + ((lane >> 4) & 1) * 8) * PH_ + ((lane >> 3) & 1) * 8) * 2;

    float acc[4][4][4];
#pragma unroll
    for (int i = 0; i < 4; i++)
#pragma unroll
        for (int j = 0; j < 4; j++)
#pragma unroll
            for (int r = 0; r < 4; r++) acc[i][j][r] = 0.0f;

    constexpr int nch = K / BK_;

    {
#pragma unroll
        for (int i = 0; i < 2; i++) {
            int row = gr + i * 64;
            cp_async16(as_base + (row * PH_ + gc) * 2, &A[(size_t)(m0 + row) * K + gc]);
            cp_async16(bs_base + (row * PH_ + gc) * 2, &Bt[(size_t)(n0 + row) * K + gc]);
        }
        asm volatile("cp.async.commit_group;");
    }

#pragma unroll
    for (int c = 0; c < nch; c++) {
        asm volatile("cp.async.wait_group 0;");
        __syncthreads();

        if (c + 1 < nch) {
            const int k0 = (c + 1) * BK_;
            const int buf = (c + 1) & 1;
            const uint32_t ab = as_base + buf * BM_ * PH_ * 2;
            const uint32_t bb = bs_base + buf * BN_ * PH_ * 2;
#pragma unroll
            for (int i = 0; i < 2; i++) {
                int row = gr + i * 64;
                cp_async16(ab + (row * PH_ + gc) * 2, &A[(size_t)(m0 + row) * K + k0 + gc]);
                cp_async16(bb + (row * PH_ + gc) * 2, &Bt[(size_t)(n0 + row) * K + k0 + gc]);
            }
            asm volatile("cp.async.commit_group;");
        }

        const uint32_t abuf = as_base + (c & 1) * BM_ * PH_ * 2 + a_lane;
        const uint32_t bbuf = bs_base + (c & 1) * BN_ * PH_ * 2 + b_lane;

#pragma unroll
        for (int ks = 0; ks < 2; ks++) {
            uint32_t afr[4][4];
#pragma unroll
            for (int mi = 0; mi < 4; mi++)
                LDMX4(afr[mi][0], afr[mi][1], afr[mi][2], afr[mi][3],
                      abuf + mi * 16 * PH_ * 2 + ks * 32);
            uint32_t bfr[4][2];
#pragma unroll
            for (int p = 0; p < 2; p++) {
                uint32_t t0, t1, t2, t3;
                LDMX4(t0, t1, t2, t3, bbuf + p * 16 * PH_ * 2 + ks * 32);
                bfr[2 * p][0] = t0; bfr[2 * p][1] = t1;
                bfr[2 * p + 1][0] = t2; bfr[2 * p + 1][1] = t3;
            }
#pragma unroll
            for (int mi = 0; mi < 4; mi++)
#pragma unroll
                for (int nj = 0; nj < 4; nj++)
                    mma_f16(acc[mi][nj], afr[mi], bfr[nj]);
        }
        __syncthreads();
    }

#pragma unroll
    for (int mi = 0; mi < 4; mi++) {
        const int r0 = m0 + wm + mi * 16 + lr;
#pragma unroll
        for (int nj = 0; nj < 4; nj++) {
            const int col = n0 + wn + nj * 8 + lc * 2;
            float2 b2 = make_float2(0.f, 0.f);
            if (HAS_BIAS) b2 = *(const float2*)&bias[col];
            float2 v0 = make_float2(acc[mi][nj][0] + b2.x, acc[mi][nj][1] + b2.y);
            float2 v1 = make_float2(acc[mi][nj][2] + b2.x, acc[mi][nj][3] + b2.y);
            *(float2*)&Cm[(size_t)r0 * N + col] = v0;
            *(float2*)&Cm[(size_t)(r0 + 8) * N + col] = v1;
        }
    }
}

// ================= fused qkv-GEMM + ctx kernel (ldmatrix mainloop) =================
#define KVN_ 288
#define STH_ 136     // eT/vT row stride in halves (68 words)
#define KV_SMEM_BYTES ((2 * BM_ * PH_ + 2 * KVN_ * PH_) * 2)   // 66560

__global__ void __launch_bounds__(256, 1)
kv_ctx_kernel()
{
    extern __shared__ __half smemh[];
    __half* As = smemh;                          // [2][128][PH_]
    __half* Bs = smemh + 2 * BM_ * PH_;          // [2][288][PH_]
    __half* eT = smemh;                          // [96][STH_]  (epilogue view)
    __half* vT = smemh + 96 * STH_;              // [96][STH_]

    const int tid = threadIdx.x;
    const int wid = tid >> 5;
    const int lane = tid & 31;
    const int cg = blockIdx.x;
    const int ss = blockIdx.y;
    const int lr = lane >> 2;
    const int lc = lane & 3;
    const int wm = (wid & 1) * 64;
    const int wn = (wid >> 1) * 72;   // 4 warps over N=288
    const int gr = tid >> 2;          // 0..63
    const int gc = (tid & 3) * 8;

    const uint32_t as_base = smem_u32(As);
    const uint32_t bs_base = smem_u32(Bs);

    const int lrow = lane & 7;
    const uint32_t a_lane = ((wm + lrow + ((lane >> 3) & 1) * 8) * PH_ + ((lane >> 4) & 1) * 8) * 2;
    const uint32_t b_lane = ((wn + lrow + ((lane >> 4) & 1) * 8) * PH_ + ((lane >> 3) & 1) * 8) * 2;

    const __half* Wq = g_Wtqh + (size_t)(cg * 96) * D_;
    const __half* Wk = g_Wtqh + (size_t)(D_ + cg * 96) * D_;
    const __half* Wv = g_Wtqh + (size_t)(2 * D_ + cg * 96) * D_;

    const int batch = ss / 32;

    float ctxa[5][4];
#pragma unroll
    for (int i = 0; i < 5; i++)
#pragma unroll
        for (int r = 0; r < 4; r++) ctxa[i][r] = 0.0f;
    float ssum = 0.0f;

    for (int rb = 0; rb < 4; rb++) {
        const size_t tok0 = ((size_t)ss * 4 + rb) * 128;
        const __half* A = g_xh + tok0 * D_;

        float acc[4][9][4];
#pragma unroll
        for (int i = 0; i < 4; i++)
#pragma unroll
            for (int j = 0; j < 9; j++)
#pragma unroll
                for (int r = 0; r < 4; r++) acc[i][j][r] = 0.0f;

        {
#pragma unroll
            for (int i = 0; i < 2; i++) {
                int row = gr + i * 64;
                cp_async16(as_base + (row * PH_ + gc) * 2, &A[(size_t)row * D_ + gc]);
            }
#pragma unroll
            for (int i = 0; i < 5; i++) {
                int row = gr + i * 64;
                if (row < KVN_) {
                    const __half* src = (row < 96) ? &Wq[(size_t)row * D_ + gc]
                                     : (row < 192) ? &Wk[(size_t)(row - 96) * D_ + gc]
                                                   : &Wv[(size_t)(row - 192) * D_ + gc];
                    cp_async16(bs_base + (row * PH_ + gc) * 2, src);
                }
            }
            asm volatile("cp.async.commit_group;");
        }

#pragma unroll
        for (int c = 0; c < D_ / BK_; c++) {
            asm volatile("cp.async.wait_group 0;");
            __syncthreads();

            if (c + 1 < D_ / BK_) {
                const int k0 = (c + 1) * BK_;
                const int buf = (c + 1) & 1;
                const uint32_t ab = as_base + buf * BM_ * PH_ * 2;
                const uint32_t bb = bs_base + buf * KVN_ * PH_ * 2;
#pragma unroll
                for (int i = 0; i < 2; i++) {
                    int row = gr + i * 64;
                    cp_async16(ab + (row * PH_ + gc) * 2, &A[(size_t)row * D_ + k0 + gc]);
                }
#pragma unroll
                for (int i = 0; i < 5; i++) {
                    int row = gr + i * 64;
                    if (row < KVN_) {
                        const __half* src = (row < 96) ? &Wq[(size_t)row * D_ + k0 + gc]
                                         : (row < 192) ? &Wk[(size_t)(row - 96) * D_ + k0 + gc]
                                                       : &Wv[(size_t)(row - 192) * D_ + k0 + gc];
                        cp_async16(bb + (row * PH_ + gc) * 2, src);
                    }
                }
                asm volatile("cp.async.commit_group;");
            }

            const uint32_t abuf = as_base + (c & 1) * BM_ * PH_ * 2 + a_lane;
            const uint32_t bbuf = bs_base + (c & 1) * KVN_ * PH_ * 2 + b_lane;

#pragma unroll
            for (int ks = 0; ks < 2; ks++) {
                uint32_t afr[4][4];
#pragma unroll
                for (int mi = 0; mi < 4; mi++)
                    LDMX4(afr[mi][0], afr[mi][1], afr[mi][2], afr[mi][3],
                          abuf + mi * 16 * PH_ * 2 + ks * 32);
                uint32_t bfr[9][2];
#pragma unroll
                for (int p = 0; p < 4; p++) {
                    uint32_t t0, t1, t2, t3;
                    LDMX4(t0, t1, t2, t3, bbuf + p * 16 * PH_ * 2 + ks * 32);
                    bfr[2 * p][0] = t0; bfr[2 * p][1] = t1;
                    bfr[2 * p + 1][0] = t2; bfr[2 * p + 1][1] = t3;
                }
                LDMX2(bfr[8][0], bfr[8][1], bbuf + 4 * 16 * PH_ * 2 + ks * 32);
#pragma unroll
                for (int mi = 0; mi < 4; mi++)
#pragma unroll
                    for (int nj = 0; nj < 9; nj++)
                        mma_f16(acc[mi][nj], afr[mi], bfr[nj]);
            }
            __syncthreads();
        }

        // ---- epilogue: q -> exp -> gmem fp16 ; k -> exp -> eT ; v -> vT ----
        {
            __half* eqb = g_eqh + tok0 * D_ + cg * 96;
#pragma unroll
            for (int nj = 0; nj < 9; nj++) {
                const int chbase = wn + nj * 8;
                if (chbase < 96) {
                    const int ch = chbase + lc * 2;
#pragma unroll
                    for (int mi = 0; mi < 4; mi++) {
                        int tl = wm + mi * 16 + lr;
                        __half2 v0 = __floats2half2_rn(__expf(acc[mi][nj][0]), __expf(acc[mi][nj][1]));
                        __half2 v1 = __floats2half2_rn(__expf(acc[mi][nj][2]), __expf(acc[mi][nj][3]));
                        *(__half2*)&eqb[(size_t)tl * D_ + ch] = v0;
                        *(__half2*)&eqb[(size_t)(tl + 8) * D_ + ch] = v1;
                    }
                } else if (chbase < 192) {
#pragma unroll
                    for (int mi = 0; mi < 4; mi++) {
#pragma unroll
                        for (int r = 0; r < 4; r++) {
                            int ch = chbase - 96 + lc * 2 + (r & 1);
                            int tl = wm + mi * 16 + lr + ((r >> 1) ? 8 : 0);
                            eT[ch * STH_ + tl] = __float2half_rn(__expf(acc[mi][nj][r]));
                        }
                    }
                } else {
#pragma unroll
                    for (int mi = 0; mi < 4; mi++) {
#pragma unroll
                        for (int r = 0; r < 4; r++) {
                            int ch = chbase - 192 + lc * 2 + (r & 1);
                            int tl = wm + mi * 16 + lr + ((r >> 1) ? 8 : 0);
                            vT[ch * STH_ + tl] = __float2half_rn(acc[mi][nj][r]);
                        }
                    }
                }
            }
        }
        __syncthreads();

        // ---- ctx += e^T v via fp16 MMA: 36 m16n8 tiles, k=128 (8 k16-steps) ----
        const uint32_t* eTw = (const uint32_t*)eT;
        const uint32_t* vTw = (const uint32_t*)vT;
#pragma unroll
        for (int i = 0; i < 5; i++) {
            int t = wid + 8 * i;
            if (t < 36) {
                int head = t / 18, rem = t % 18;
                int mi = rem / 6, nj = rem % 6;
                const int ar = head * 48 + mi * 16;
                const int br = head * 48 + nj * 8;
#pragma unroll
                for (int ks = 0; ks < 8; ks++) {
                    const int kw = ks * 8 + lc;
                    uint32_t a[4], b[2];
                    a[0] = eTw[(ar + lr) * 68 + kw];
                    a[1] = eTw[(ar + lr + 8) * 68 + kw];
                    a[2] = eTw[(ar + lr) * 68 + kw + 4];
                    a[3] = eTw[(ar + lr + 8) * 68 + kw + 4];
                    b[0] = vTw[(br + lr) * 68 + kw];
                    b[1] = vTw[(br + lr) * 68 + kw + 4];
                    mma_f16(ctxa[i], a, b);
                }
            }
        }

        // ---- per-channel exp-sum ----
        if (tid < 96) {
            const uint32_t* row = (const uint32_t*)(eT + tid * STH_);
            float s = 0.0f;
#pragma unroll
            for (int j = 0; j < 64; j++) {
                uint32_t w = row[j];
                float2 f = __half22float2(*(const __half2*)&w);
                s += f.x + f.y;
            }
            ssum += s;
        }
        __syncthreads();
    }

    // ---- atomics ----
#pragma unroll
    for (int i = 0; i < 5; i++) {
        int t = wid + 8 * i;
        if (t < 36) {
            int head = t / 18, rem = t % 18;
            int mi = rem / 6, nj = rem % 6;
            int bh = (batch * H_ + cg * 2 + head);
#pragma unroll
            for (int r = 0; r < 4; r++) {
                int c = mi * 16 + lr + ((r >> 1) ? 8 : 0);
                int d = nj * 8 + lc * 2 + (r & 1);
                atomicAdd(&g_ctx[((size_t)bh * C_ + c) * C_ + d], ctxa[i][r]);
            }
        }
    }
    if (tid < 96) {
        int head = tid / 48;
        atomicAdd(&g_sum[(batch * H_ + cg * 2 + head) * C_ + tid % 48], ssum);
    }
}

// ================= global context normalization (one-shot, fp16 out) =================
#define ACT_STH 56
__global__ void ctxn_norm_kernel()
{
    __shared__ float sinv[C_];
    const int bh = blockIdx.x;
    if (threadIdx.x < C_) sinv[threadIdx.x] = 1.0f / g_sum[bh * C_ + threadIdx.x];
    __syncthreads();
    const float* cb = g_ctx + (size_t)bh * (C_ * C_);
    __half* ob = g_ctxnTh + (size_t)bh * (C_ * ACT_STH);
    for (int i = threadIdx.x; i < C_ * C_; i += 256) {
        int c = i / C_, d = i % C_;
        ob[d * ACT_STH + c] = __float2half_rn(cb[i] * sinv[c]);
    }
}

// ================= fp16 HMMA attn: CTA = 128 tokens x 1 head, 128 threads =================
__global__ void __launch_bounds__(128, 4)
attn_tc_kernel()
{
    __shared__ __half eq[128 * ACT_STH];      // 14336 B
    __shared__ __half ctxT[C_ * ACT_STH];     // 5376 B
    __shared__ float srow[128];

    const int tid = threadIdx.x;
    const int wid = tid >> 5;
    const int lane = tid & 31;
    const int lr = lane >> 2;
    const int lc = lane & 3;
    const int h = blockIdx.x & 7;
    const size_t tok0 = (size_t)(blockIdx.x >> 3) * 128;
    const int batch = (int)(tok0 / SEQ_);

    {
        const uint2* src = (const uint2*)(g_ctxnTh + ((size_t)batch * H_ + h) * (C_ * ACT_STH));
        uint2* dst = (uint2*)ctxT;
#pragma unroll
        for (int i = tid; i < C_ * ACT_STH / 4; i += 128) dst[i] = src[i];
    }
    {
        const __half* qb = g_eqh + tok0 * D_ + h * C_;
        for (int i = tid; i < 128 * 12; i += 128) {
            int r = i / 12, c4 = i % 12;
            uint2 v = *(const uint2*)&qb[(size_t)r * D_ + c4 * 4];
            *(uint2*)&eq[r * ACT_STH + c4 * 4] = v;
        }
    }
    __syncthreads();
    {
        const uint32_t* rp = (const uint32_t*)(eq + tid * ACT_STH);
        float s = 0.0f;
#pragma unroll
        for (int j = 0; j < 24; j++) {
            uint32_t w = rp[j];
            float2 f = __half22float2(*(const __half2*)&w);
            s += f.x + f.y;
        }
        srow[tid] = 1.0f / s;
    }
    __syncthreads();

    float acc[2][6][4];
#pragma unroll
    for (int i = 0; i < 2; i++)
#pragma unroll
        for (int j = 0; j < 6; j++)
#pragma unroll
            for (int r = 0; r < 4; r++) acc[i][j][r] = 0.0f;

    const uint32_t* eqw = (const uint32_t*)(eq + wid * 32 * ACT_STH);
    const uint32_t* cw = (const uint32_t*)ctxT;
#pragma unroll
    for (int ks = 0; ks < 3; ks++) {
        const int kw = ks * 8 + lc;
        uint32_t afr[2][4];
#pragma unroll
        for (int mi = 0; mi < 2; mi++) {
            int r = mi * 16 + lr;
            afr[mi][0] = eqw[r * 28 + kw];
            afr[mi][1] = eqw[(r + 8) * 28 + kw];
            afr[mi][2] = eqw[r * 28 + kw + 4];
            afr[mi][3] = eqw[(r + 8) * 28 + kw + 4];
        }
        uint32_t bfr[6][2];
#pragma unroll
        for (int nj = 0; nj < 6; nj++) {
            int nn = nj * 8 + lr;
            bfr[nj][0] = cw[nn * 28 + kw];
            bfr[nj][1] = cw[nn * 28 + kw + 4];
        }
#pragma unroll
        for (int mi = 0; mi < 2; mi++)
#pragma unroll
            for (int nj = 0; nj < 6; nj++)
                mma_f16(acc[mi][nj], afr[mi], bfr[nj]);
    }

    __half* ob = g_attnh + tok0 * D_ + h * C_;
#pragma unroll
    for (int mi = 0; mi < 2; mi++) {
        const int ra = wid * 32 + mi * 16 + lr;
        const float sa = srow[ra];
        const float sb = srow[ra + 8];
#pragma unroll
        for (int nj = 0; nj < 6; nj++) {
            const int col = nj * 8 + lc * 2;
            __half2 v0 = __floats2half2_rn(acc[mi][nj][0] * sa, acc[mi][nj][1] * sa);
            __half2 v1 = __floats2half2_rn(acc[mi][nj][2] * sb, acc[mi][nj][3] * sb);
            *(__half2*)&ob[(size_t)ra * D_ + col] = v0;
            *(__half2*)&ob[(size_t)(ra + 8) * D_ + col] = v1;
        }
    }
}

// ---------------- launch ----------------
extern "C" void kernel_launch(void* const* d_in, const int* in_sizes, int n_in,
                              void* d_out, int out_size)
{
    const float* x     = (const float*)d_in[0];
    const float* Wqkv  = (const float*)d_in[1];
    const float* Wproj = (const float*)d_in[2];
    const float* bproj = (const float*)d_in[3];
    float* out = (float*)d_out;

    __half *p_xh, *p_attnh, *p_wtqh, *p_wtph;
    cudaGetSymbolAddress((void**)&p_xh, g_xh);
    cudaGetSymbolAddress((void**)&p_attnh, g_attnh);
    cudaGetSymbolAddress((void**)&p_wtqh, g_Wtqh);
    cudaGetSymbolAddress((void**)&p_wtph, g_Wtph);

    const int gemm_smem = 4 * BM_ * PH_ * 2;     // 40960
    cudaFuncSetAttribute(gemm_f16<D_, D_, 1>, cudaFuncAttributeMaxDynamicSharedMemorySize, gemm_smem);
    cudaFuncSetAttribute(kv_ctx_kernel, cudaFuncAttributeMaxDynamicSharedMemorySize, KV_SMEM_BYTES);

    // 0) prepasses
    zero_ctx_kernel<<<(B_ * H_ * C_ * C_ + 255) / 256, 256>>>();
    {
        int n4 = TOK_ * D_ / 4;
        round_f16_kernel<<<(n4 + 255) / 256, 256>>>((const float4*)x, (uint2*)p_xh, n4);
    }
    transpose_f16_kernel<<<dim3(3 * D_ / 32, D_ / 32), dim3(32, 8)>>>(Wqkv, p_wtqh, D_, 3 * D_);
    transpose_f16_kernel<<<dim3(D_ / 32, D_ / 32), dim3(32, 8)>>>(Wproj, p_wtph, D_, D_);

    // 1) fused qkv-GEMM + exp + context accumulation (writes g_eqh, g_ctx, g_sum)
    {
        dim3 grid(4, 256);
        kv_ctx_kernel<<<grid, 256, KV_SMEM_BYTES>>>();
    }

    // 2) one-shot context normalization
    ctxn_norm_kernel<<<B_ * H_, 256>>>();

    // 3) fp16 HMMA attn (reads g_eqh, writes g_attnh)
    attn_tc_kernel<<<(TOK_ / 128) * H_, 128>>>();

    // 4) out = attn @ W_proj + b_proj
    {
        dim3 grid(D_ / BN_, TOK_ / BM_);
        gemm_f16<D_, D_, 1><<<grid, 256, gemm_smem>>>(p_attnh, p_wtph, bproj, out);
    }
}

// round 13
// speedup vs baseline: 2.1562x; 1.0822x over previous
#include <cuda_runtime.h>
#include <cuda_fp16.h>
#include <math.h>
#include <stdint.h>

// Problem constants
#define B_      8
#define SEQ_    16384
#define D_      384
#define H_      8
#define C_      48
#define TOK_    (B_ * SEQ_)          // 131072

// ---------------- scratch (static device globals; no allocs allowed) ----------------
__device__ __half g_eqh[(size_t)TOK_ * D_];          // 100 MB : exp(q) fp16
__device__ __half g_xh[(size_t)TOK_ * D_];           // 100 MB : x rounded to fp16
__device__ float  g_ctx[B_ * H_ * C_ * C_];          // unnormalized k^T v context
__device__ float  g_sum[B_ * H_ * C_];               // sum of exp(k) over tokens
__device__ __half g_ctxnTh[B_ * H_ * C_ * 56];       // normalized, transposed, fp16, padded
__device__ __half g_Wtqh[3 * D_ * D_];               // W_qkv^T, fp16  [1152][384]
__device__ __half g_Wtph[D_ * D_];                   // W_proj^T, fp16

__device__ __forceinline__ uint32_t smem_u32(const void* p) {
    uint32_t a;
    asm("{ .reg .u64 t; cvta.to.shared.u64 t, %1; cvt.u32.u64 %0, t; }" : "=r"(a) : "l"(p));
    return a;
}
__device__ __forceinline__ void cp_async16(uint32_t dst, const void* src) {
    asm volatile("cp.async.cg.shared.global [%0], [%1], 16;" :: "r"(dst), "l"(src));
}
__device__ __forceinline__ void mma_f16(float* c, const uint32_t* a, const uint32_t* b) {
    asm volatile(
        "mma.sync.aligned.m16n8k16.row.col.f32.f16.f16.f32 "
        "{%0,%1,%2,%3}, {%4,%5,%6,%7}, {%8,%9}, {%0,%1,%2,%3};"
        : "+f"(c[0]), "+f"(c[1]), "+f"(c[2]), "+f"(c[3])
        : "r"(a[0]), "r"(a[1]), "r"(a[2]), "r"(a[3]), "r"(b[0]), "r"(b[1]));
}
#define LDMX4(r0, r1, r2, r3, addr) \
    asm volatile("ldmatrix.sync.aligned.m8n8.x4.shared.b16 {%0,%1,%2,%3}, [%4];" \
        : "=r"(r0), "=r"(r1), "=r"(r2), "=r"(r3) : "r"(addr))
#define LDMX2(r0, r1, addr) \
    asm volatile("ldmatrix.sync.aligned.m8n8.x2.shared.b16 {%0,%1}, [%2];" \
        : "=r"(r0), "=r"(r1) : "r"(addr))

// ---------------- round x to fp16 (streaming) + zero accumulators ----------------
__global__ void round_f16_kernel(const float4* __restrict__ src, uint2* __restrict__ dst, int n4) {
    int i = blockIdx.x * 256 + threadIdx.x;
    if (i < B_ * H_ * C_ * C_) g_ctx[i] = 0.0f;
    if (i < B_ * H_ * C_)      g_sum[i] = 0.0f;
    if (i < n4) {
        float4 v = src[i];
        __half2 lo = __floats2half2_rn(v.x, v.y);
        __half2 hi = __floats2half2_rn(v.z, v.w);
        uint2 o;
        o.x = *(uint32_t*)&lo;
        o.y = *(uint32_t*)&hi;
        dst[i] = o;
    }
}

// ---------------- weight transpose + fp16 round: src[R][Ccols] -> dst[Ccols][R] ----------------
__global__ void transpose_f16_kernel(const float* __restrict__ src, __half* __restrict__ dst,
                                     int R, int Ccols) {
    __shared__ float t[32][33];
    int bx = blockIdx.x * 32, by = blockIdx.y * 32;
    int tx = threadIdx.x, ty = threadIdx.y;
#pragma unroll
    for (int j = 0; j < 32; j += 8)
        t[ty + j][tx] = src[(size_t)(by + ty + j) * Ccols + bx + tx];
    __syncthreads();
#pragma unroll
    for (int j = 0; j < 32; j += 8)
        dst[(size_t)(bx + ty + j) * R + by + tx] = __float2half_rn(t[tx][ty + j]);
}

#define BM_ 128
#define BK_ 32            // halves per chunk
#define PH_ 40            // halves per smem row slot

// ================= fused qkv-GEMM + ctx kernel (ldmatrix mainloop) — unchanged R12 =================
#define KVN_ 288
#define STH_ 136     // eT/vT row stride in halves (68 words)
#define KV_SMEM_BYTES ((2 * BM_ * PH_ + 2 * KVN_ * PH_) * 2)   // 66560

__global__ void __launch_bounds__(256, 1)
kv_ctx_kernel()
{
    extern __shared__ __half smemh[];
    __half* As = smemh;                          // [2][128][PH_]
    __half* Bs = smemh + 2 * BM_ * PH_;          // [2][288][PH_]
    __half* eT = smemh;                          // [96][STH_]  (epilogue view)
    __half* vT = smemh + 96 * STH_;              // [96][STH_]

    const int tid = threadIdx.x;
    const int wid = tid >> 5;
    const int lane = tid & 31;
    const int cg = blockIdx.x;
    const int ss = blockIdx.y;
    const int lr = lane >> 2;
    const int lc = lane & 3;
    const int wm = (wid & 1) * 64;
    const int wn = (wid >> 1) * 72;   // 4 warps over N=288
    const int gr = tid >> 2;          // 0..63
    const int gc = (tid & 3) * 8;

    const uint32_t as_base = smem_u32(As);
    const uint32_t bs_base = smem_u32(Bs);

    const int lrow = lane & 7;
    const uint32_t a_lane = ((wm + lrow + ((lane >> 3) & 1) * 8) * PH_ + ((lane >> 4) & 1) * 8) * 2;
    const uint32_t b_lane = ((wn + lrow + ((lane >> 4) & 1) * 8) * PH_ + ((lane >> 3) & 1) * 8) * 2;

    const __half* Wq = g_Wtqh + (size_t)(cg * 96) * D_;
    const __half* Wk = g_Wtqh + (size_t)(D_ + cg * 96) * D_;
    const __half* Wv = g_Wtqh + (size_t)(2 * D_ + cg * 96) * D_;

    const int batch = ss / 32;

    float ctxa[5][4];
#pragma unroll
    for (int i = 0; i < 5; i++)
#pragma unroll
        for (int r = 0; r < 4; r++) ctxa[i][r] = 0.0f;
    float ssum = 0.0f;

    for (int rb = 0; rb < 4; rb++) {
        const size_t tok0 = ((size_t)ss * 4 + rb) * 128;
        const __half* A = g_xh + tok0 * D_;

        float acc[4][9][4];
#pragma unroll
        for (int i = 0; i < 4; i++)
#pragma unroll
            for (int j = 0; j < 9; j++)
#pragma unroll
                for (int r = 0; r < 4; r++) acc[i][j][r] = 0.0f;

        {
#pragma unroll
            for (int i = 0; i < 2; i++) {
                int row = gr + i * 64;
                cp_async16(as_base + (row * PH_ + gc) * 2, &A[(size_t)row * D_ + gc]);
            }
#pragma unroll
            for (int i = 0; i < 5; i++) {
                int row = gr + i * 64;
                if (row < KVN_) {
                    const __half* src = (row < 96) ? &Wq[(size_t)row * D_ + gc]
                                     : (row < 192) ? &Wk[(size_t)(row - 96) * D_ + gc]
                                                   : &Wv[(size_t)(row - 192) * D_ + gc];
                    cp_async16(bs_base + (row * PH_ + gc) * 2, src);
                }
            }
            asm volatile("cp.async.commit_group;");
        }

#pragma unroll
        for (int c = 0; c < D_ / BK_; c++) {
            asm volatile("cp.async.wait_group 0;");
            __syncthreads();

            if (c + 1 < D_ / BK_) {
                const int k0 = (c + 1) * BK_;
                const int buf = (c + 1) & 1;
                const uint32_t ab = as_base + buf * BM_ * PH_ * 2;
                const uint32_t bb = bs_base + buf * KVN_ * PH_ * 2;
#pragma unroll
                for (int i = 0; i < 2; i++) {
                    int row = gr + i * 64;
                    cp_async16(ab + (row * PH_ + gc) * 2, &A[(size_t)row * D_ + k0 + gc]);
                }
#pragma unroll
                for (int i = 0; i < 5; i++) {
                    int row = gr + i * 64;
                    if (row < KVN_) {
                        const __half* src = (row < 96) ? &Wq[(size_t)row * D_ + k0 + gc]
                                         : (row < 192) ? &Wk[(size_t)(row - 96) * D_ + k0 + gc]
                                                       : &Wv[(size_t)(row - 192) * D_ + k0 + gc];
                        cp_async16(bb + (row * PH_ + gc) * 2, src);
                    }
                }
                asm volatile("cp.async.commit_group;");
            }

            const uint32_t abuf = as_base + (c & 1) * BM_ * PH_ * 2 + a_lane;
            const uint32_t bbuf = bs_base + (c & 1) * KVN_ * PH_ * 2 + b_lane;

#pragma unroll
            for (int ks = 0; ks < 2; ks++) {
                uint32_t afr[4][4];
#pragma unroll
                for (int mi = 0; mi < 4; mi++)
                    LDMX4(afr[mi][0], afr[mi][1], afr[mi][2], afr[mi][3],
                          abuf + mi * 16 * PH_ * 2 + ks * 32);
                uint32_t bfr[9][2];
#pragma unroll
                for (int p = 0; p < 4; p++) {
                    uint32_t t0, t1, t2, t3;
                    LDMX4(t0, t1, t2, t3, bbuf + p * 16 * PH_ * 2 + ks * 32);
                    bfr[2 * p][0] = t0; bfr[2 * p][1] = t1;
                    bfr[2 * p + 1][0] = t2; bfr[2 * p + 1][1] = t3;
                }
                LDMX2(bfr[8][0], bfr[8][1], bbuf + 4 * 16 * PH_ * 2 + ks * 32);
#pragma unroll
                for (int mi = 0; mi < 4; mi++)
#pragma unroll
                    for (int nj = 0; nj < 9; nj++)
                        mma_f16(acc[mi][nj], afr[mi], bfr[nj]);
            }
            __syncthreads();
        }

        // ---- epilogue: q -> exp -> gmem fp16 ; k -> exp -> eT ; v -> vT ----
        {
            __half* eqb = g_eqh + tok0 * D_ + cg * 96;
#pragma unroll
            for (int nj = 0; nj < 9; nj++) {
                const int chbase = wn + nj * 8;
                if (chbase < 96) {
                    const int ch = chbase + lc * 2;
#pragma unroll
                    for (int mi = 0; mi < 4; mi++) {
                        int tl = wm + mi * 16 + lr;
                        __half2 v0 = __floats2half2_rn(__expf(acc[mi][nj][0]), __expf(acc[mi][nj][1]));
                        __half2 v1 = __floats2half2_rn(__expf(acc[mi][nj][2]), __expf(acc[mi][nj][3]));
                        *(__half2*)&eqb[(size_t)tl * D_ + ch] = v0;
                        *(__half2*)&eqb[(size_t)(tl + 8) * D_ + ch] = v1;
                    }
                } else if (chbase < 192) {
#pragma unroll
                    for (int mi = 0; mi < 4; mi++) {
#pragma unroll
                        for (int r = 0; r < 4; r++) {
                            int ch = chbase - 96 + lc * 2 + (r & 1);
                            int tl = wm + mi * 16 + lr + ((r >> 1) ? 8 : 0);
                            eT[ch * STH_ + tl] = __float2half_rn(__expf(acc[mi][nj][r]));
                        }
                    }
                } else {
#pragma unroll
                    for (int mi = 0; mi < 4; mi++) {
#pragma unroll
                        for (int r = 0; r < 4; r++) {
                            int ch = chbase - 192 + lc * 2 + (r & 1);
                            int tl = wm + mi * 16 + lr + ((r >> 1) ? 8 : 0);
                            vT[ch * STH_ + tl] = __float2half_rn(acc[mi][nj][r]);
                        }
                    }
                }
            }
        }
        __syncthreads();

        // ---- ctx += e^T v via fp16 MMA: 36 m16n8 tiles, k=128 (8 k16-steps) ----
        const uint32_t* eTw = (const uint32_t*)eT;
        const uint32_t* vTw = (const uint32_t*)vT;
#pragma unroll
        for (int i = 0; i < 5; i++) {
            int t = wid + 8 * i;
            if (t < 36) {
                int head = t / 18, rem = t % 18;
                int mi = rem / 6, nj = rem % 6;
                const int ar = head * 48 + mi * 16;
                const int br = head * 48 + nj * 8;
#pragma unroll
                for (int ks = 0; ks < 8; ks++) {
                    const int kw = ks * 8 + lc;
                    uint32_t a[4], b[2];
                    a[0] = eTw[(ar + lr) * 68 + kw];
                    a[1] = eTw[(ar + lr + 8) * 68 + kw];
                    a[2] = eTw[(ar + lr) * 68 + kw + 4];
                    a[3] = eTw[(ar + lr + 8) * 68 + kw + 4];
                    b[0] = vTw[(br + lr) * 68 + kw];
                    b[1] = vTw[(br + lr) * 68 + kw + 4];
                    mma_f16(ctxa[i], a, b);
                }
            }
        }

        // ---- per-channel exp-sum ----
        if (tid < 96) {
            const uint32_t* row = (const uint32_t*)(eT + tid * STH_);
            float s = 0.0f;
#pragma unroll
            for (int j = 0; j < 64; j++) {
                uint32_t w = row[j];
                float2 f = __half22float2(*(const __half2*)&w);
                s += f.x + f.y;
            }
            ssum += s;
        }
        __syncthreads();
    }

    // ---- atomics ----
#pragma unroll
    for (int i = 0; i < 5; i++) {
        int t = wid + 8 * i;
        if (t < 36) {
            int head = t / 18, rem = t % 18;
            int mi = rem / 6, nj = rem % 6;
            int bh = (batch * H_ + cg * 2 + head);
#pragma unroll
            for (int r = 0; r < 4; r++) {
                int c = mi * 16 + lr + ((r >> 1) ? 8 : 0);
                int d = nj * 8 + lc * 2 + (r & 1);
                atomicAdd(&g_ctx[((size_t)bh * C_ + c) * C_ + d], ctxa[i][r]);
            }
        }
    }
    if (tid < 96) {
        int head = tid / 48;
        atomicAdd(&g_sum[(batch * H_ + cg * 2 + head) * C_ + tid % 48], ssum);
    }
}

// ================= global context normalization (one-shot, fp16 out) =================
#define ACT_STH 56
__global__ void ctxn_norm_kernel()
{
    __shared__ float sinv[C_];
    const int bh = blockIdx.x;
    if (threadIdx.x < C_) sinv[threadIdx.x] = 1.0f / g_sum[bh * C_ + threadIdx.x];
    __syncthreads();
    const float* cb = g_ctx + (size_t)bh * (C_ * C_);
    __half* ob = g_ctxnTh + (size_t)bh * (C_ * ACT_STH);
    for (int i = threadIdx.x; i < C_ * C_; i += 256) {
        int c = i / C_, d = i % C_;
        ob[d * ACT_STH + c] = __float2half_rn(cb[i] * sinv[c]);
    }
}

// ================= fused attn + proj: CTA = 64 tokens x full N=384 =================
// Phases: cp.async(eq, ctxT, W chunk0) -> rowsums -> per-warp head attn (in-place) ->
//         12-chunk ldmatrix proj mainloop -> fp32 out + bias.
#define AQ_ST 392                            // eq row stride in halves (196 words)
#define AP_EQ_B    (64 * AQ_ST * 2)          // 50176
#define AP_CTX_B   (H_ * C_ * ACT_STH * 2)   // 43008
#define AP_W_B     (2 * D_ * PH_ * 2)        // 61440
#define AP_SMEM_BYTES (AP_EQ_B + AP_CTX_B + AP_W_B + 2048)

__global__ void __launch_bounds__(256, 1)
attn_proj_kernel(const float* __restrict__ bias, float* __restrict__ out)
{
    extern __shared__ char smem[];
    __half* eqA  = (__half*)smem;                       // [64][AQ_ST]
    __half* ctxs = (__half*)(smem + AP_EQ_B);           // [8*48][ACT_STH]
    __half* wbuf = (__half*)(smem + AP_EQ_B + AP_CTX_B);// [2][384][PH_]
    float*  srow = (float*)(smem + AP_EQ_B + AP_CTX_B + AP_W_B);  // [64][8]

    const int tid = threadIdx.x;
    const int wid = tid >> 5;
    const int lane = tid & 31;
    const int lr = lane >> 2;
    const int lc = lane & 3;
    const size_t tok0 = (size_t)blockIdx.x * 64;
    const int batch = blockIdx.x / (SEQ_ / 64);

    const uint32_t eq_base = smem_u32(eqA);
    const uint32_t ctx_base = smem_u32(ctxs);
    const uint32_t w_base = smem_u32(wbuf);

    const int gr = tid >> 2;          // 0..63
    const int gc = (tid & 3) * 8;

    // ---- group 1: eq tile + ctxT ----
    {
        const __half* eqg = g_eqh + tok0 * D_;
#pragma unroll
        for (int i = 0; i < 12; i++) {
            int col = gc + i * 32;
            cp_async16(eq_base + (gr * AQ_ST + col) * 2, &eqg[(size_t)gr * D_ + col]);
        }
        const __half* cg = g_ctxnTh + (size_t)batch * (H_ * C_ * ACT_STH);
        for (int i = tid; i < H_ * C_ * (ACT_STH / 8); i += 256) {
            int r = i / 7, u = i % 7;
            cp_async16(ctx_base + (r * ACT_STH + u * 8) * 2, &cg[(size_t)r * ACT_STH + u * 8]);
        }
        asm volatile("cp.async.commit_group;");
    }
    // ---- group 2: W chunk 0 ----
    {
#pragma unroll
        for (int i = 0; i < 6; i++) {
            int row = gr + i * 64;
            cp_async16(w_base + (row * PH_ + gc) * 2, &g_Wtph[(size_t)row * D_ + gc]);
        }
        asm volatile("cp.async.commit_group;");
    }
    asm volatile("cp.async.wait_group 1;");
    __syncthreads();

    // ---- rowsums: 512 (token, head) pairs ----
    for (int p = tid; p < 512; p += 256) {
        int r = p >> 3, h = p & 7;
        const uint32_t* rp = (const uint32_t*)(eqA + r * AQ_ST + h * C_);
        float s = 0.0f;
#pragma unroll
        for (int j = 0; j < 24; j++) {
            uint32_t w = rp[j];
            float2 f = __half22float2(*(const __half2*)&w);
            s += f.x + f.y;
        }
        srow[p] = 1.0f / s;
    }
    __syncthreads();

    // ---- per-warp head attn (warp w = head w), in-place on eqA cols w*48.. ----
    {
        const int h = wid;
        const uint32_t* eqw = (const uint32_t*)eqA;
        const uint32_t* cw = (const uint32_t*)ctxs;
        float acc[4][6][4];
#pragma unroll
        for (int i = 0; i < 4; i++)
#pragma unroll
            for (int j = 0; j < 6; j++)
#pragma unroll
                for (int r = 0; r < 4; r++) acc[i][j][r] = 0.0f;

#pragma unroll
        for (int ks = 0; ks < 3; ks++) {
            const int kw = ks * 8 + lc;
            uint32_t afr[4][4];
#pragma unroll
            for (int mi = 0; mi < 4; mi++) {
                int r = mi * 16 + lr;
                afr[mi][0] = eqw[r * (AQ_ST / 2) + h * 24 + kw];
                afr[mi][1] = eqw[(r + 8) * (AQ_ST / 2) + h * 24 + kw];
                afr[mi][2] = eqw[r * (AQ_ST / 2) + h * 24 + kw + 4];
                afr[mi][3] = eqw[(r + 8) * (AQ_ST / 2) + h * 24 + kw + 4];
            }
            uint32_t bfr[6][2];
#pragma unroll
            for (int nj = 0; nj < 6; nj++) {
                int nn = h * C_ + nj * 8 + lr;
                bfr[nj][0] = cw[nn * (ACT_STH / 2) + kw];
                bfr[nj][1] = cw[nn * (ACT_STH / 2) + kw + 4];
            }
#pragma unroll
            for (int mi = 0; mi < 4; mi++)
#pragma unroll
                for (int nj = 0; nj < 6; nj++)
                    mma_f16(acc[mi][nj], afr[mi], bfr[nj]);
        }
        __syncwarp();
#pragma unroll
        for (int mi = 0; mi < 4; mi++) {
            const int ra = mi * 16 + lr;
            const float sa = srow[ra * 8 + h];
            const float sb = srow[(ra + 8) * 8 + h];
#pragma unroll
            for (int nj = 0; nj < 6; nj++) {
                const int col = h * C_ + nj * 8 + lc * 2;
                __half2 v0 = __floats2half2_rn(acc[mi][nj][0] * sa, acc[mi][nj][1] * sa);
                __half2 v1 = __floats2half2_rn(acc[mi][nj][2] * sb, acc[mi][nj][3] * sb);
                *(__half2*)&eqA[ra * AQ_ST + col] = v0;
                *(__half2*)&eqA[(ra + 8) * AQ_ST + col] = v1;
            }
        }
    }
    __syncthreads();

    // ---- proj mainloop: out[64x384] = A(eqA) @ Wproj^T ; warp tile 32x96 ----
    const int wm = (wid & 1) * 32;
    const int wn = (wid >> 1) * 96;
    const int lrow = lane & 7;
    const uint32_t a_lane = eq_base + ((wm + lrow + ((lane >> 3) & 1) * 8) * AQ_ST + ((lane >> 4) & 1) * 8) * 2;
    const uint32_t b_lane = ((wn + lrow + ((lane >> 4) & 1) * 8) * PH_ + ((lane >> 3) & 1) * 8) * 2;

    float acc[2][12][4];
#pragma unroll
    for (int i = 0; i < 2; i++)
#pragma unroll
        for (int j = 0; j < 12; j++)
#pragma unroll
            for (int r = 0; r < 4; r++) acc[i][j][r] = 0.0f;

#pragma unroll
    for (int c = 0; c < 12; c++) {
        asm volatile("cp.async.wait_group 0;");
        __syncthreads();

        if (c + 1 < 12) {
            const int k0 = (c + 1) * BK_;
            const uint32_t bb = w_base + ((c + 1) & 1) * D_ * PH_ * 2;
#pragma unroll
            for (int i = 0; i < 6; i++) {
                int row = gr + i * 64;
                cp_async16(bb + (row * PH_ + gc) * 2, &g_Wtph[(size_t)row * D_ + k0 + gc]);
            }
            asm volatile("cp.async.commit_group;");
        }

        const uint32_t abuf = a_lane + c * 64;   // chunk c -> +64 bytes (32 halves)
        const uint32_t bbuf = w_base + (c & 1) * D_ * PH_ * 2 + b_lane;

#pragma unroll
        for (int ks = 0; ks < 2; ks++) {
            uint32_t afr[2][4];
#pragma unroll
            for (int mi = 0; mi < 2; mi++)
                LDMX4(afr[mi][0], afr[mi][1], afr[mi][2], afr[mi][3],
                      abuf + mi * 16 * AQ_ST * 2 + ks * 32);
            uint32_t bfr[12][2];
#pragma unroll
            for (int p = 0; p < 6; p++) {
                uint32_t t0, t1, t2, t3;
                LDMX4(t0, t1, t2, t3, bbuf + p * 16 * PH_ * 2 + ks * 32);
                bfr[2 * p][0] = t0; bfr[2 * p][1] = t1;
                bfr[2 * p + 1][0] = t2; bfr[2 * p + 1][1] = t3;
            }
#pragma unroll
            for (int mi = 0; mi < 2; mi++)
#pragma unroll
                for (int nj = 0; nj < 12; nj++)
                    mma_f16(acc[mi][nj], afr[mi], bfr[nj]);
        }
        __syncthreads();
    }

    // ---- epilogue: fp32 out + bias ----
#pragma unroll
    for (int mi = 0; mi < 2; mi++) {
        const size_t r0 = tok0 + wm + mi * 16 + lr;
#pragma unroll
        for (int nj = 0; nj < 12; nj++) {
            const int col = wn + nj * 8 + lc * 2;
            float2 b2 = *(const float2*)&bias[col];
            float2 v0 = make_float2(acc[mi][nj][0] + b2.x, acc[mi][nj][1] + b2.y);
            float2 v1 = make_float2(acc[mi][nj][2] + b2.x, acc[mi][nj][3] + b2.y);
            *(float2*)&out[r0 * D_ + col] = v0;
            *(float2*)&out[(r0 + 8) * D_ + col] = v1;
        }
    }
}

// ---------------- launch ----------------
extern "C" void kernel_launch(void* const* d_in, const int* in_sizes, int n_in,
                              void* d_out, int out_size)
{
    const float* x     = (const float*)d_in[0];
    const float* Wqkv  = (const float*)d_in[1];
    const float* Wproj = (const float*)d_in[2];
    const float* bproj = (const float*)d_in[3];
    float* out = (float*)d_out;

    __half *p_xh, *p_wtqh, *p_wtph;
    cudaGetSymbolAddress((void**)&p_xh, g_xh);
    cudaGetSymbolAddress((void**)&p_wtqh, g_Wtqh);
    cudaGetSymbolAddress((void**)&p_wtph, g_Wtph);

    cudaFuncSetAttribute(kv_ctx_kernel, cudaFuncAttributeMaxDynamicSharedMemorySize, KV_SMEM_BYTES);
    cudaFuncSetAttribute(attn_proj_kernel, cudaFuncAttributeMaxDynamicSharedMemorySize, AP_SMEM_BYTES);

    // 0) prepass: round x to fp16 (+ zero accumulators); transpose weights
    {
        int n4 = TOK_ * D_ / 4;
        round_f16_kernel<<<(n4 + 255) / 256, 256>>>((const float4*)x, (uint2*)p_xh, n4);
    }
    transpose_f16_kernel<<<dim3(3 * D_ / 32, D_ / 32), dim3(32, 8)>>>(Wqkv, p_wtqh, D_, 3 * D_);
    transpose_f16_kernel<<<dim3(D_ / 32, D_ / 32), dim3(32, 8)>>>(Wproj, p_wtph, D_, D_);

    // 1) fused qkv-GEMM + exp + context accumulation (writes g_eqh, g_ctx, g_sum)
    {
        dim3 grid(4, 256);
        kv_ctx_kernel<<<grid, 256, KV_SMEM_BYTES>>>();
    }

    // 2) one-shot context normalization
    ctxn_norm_kernel<<<B_ * H_, 256>>>();

    // 3) fused attn + proj (reads g_eqh + g_ctxnTh, writes out)
    attn_proj_kernel<<<TOK_ / 64, 256, AP_SMEM_BYTES>>>(bproj, out);
}